// round 2
// baseline (speedup 1.0000x reference)
#include <cuda_runtime.h>
#include <math.h>
#include <stdint.h>

#define VOCAB1 32001
#define DIN 512
#define DR  512
#define DF  2048
#define BB  64
#define TT  20
#define G4  2048   // 4*DR
#define KSPLIT 4

// ---------------- device scratch (static, no allocation) ----------------
__device__ __align__(16) float g_xs[TT * BB * DIN];        // xs[t][b][din]
__device__ __align__(16) float g_gx[(size_t)TT * BB * G4]; // gates_x[t][b][4r]
__device__ __align__(16) float g_h[BB * DR];
__device__ __align__(16) float g_c[BB * DR];
__device__ __align__(16) float g_hs[TT * BB * DR];         // hs[t][b][r]
__device__ __align__(16) float g_gp[KSPLIT * BB * G4];     // k-split partials
__device__ __align__(16) float g_bias2[G4];                // b_ih + b_hh
__device__ __align__(16) float g_lse[BB * TT];             // per (b,t) row lse

// ---------------- init: zero h/c, combine biases ----------------
__global__ void init_k(const float* __restrict__ b_ih, const float* __restrict__ b_hh) {
    int id = blockIdx.x * blockDim.x + threadIdx.x;
    if (id < BB * DR) { g_h[id] = 0.f; g_c[id] = 0.f; }
    if (id < G4) g_bias2[id] = b_ih[id] + b_hh[id];
}

// ---------------- embedding gather for t=1..19 (seq is int32!) ----------------
__global__ void gather_embed(const int* __restrict__ seq,
                             const float* __restrict__ embed) {
    int t = 1 + blockIdx.x;      // 1..19
    int b = blockIdx.y;          // 0..63
    int idx = seq[b * TT + t];
    if (idx < 0) idx = 0;
    if (idx > VOCAB1 - 1) idx = VOCAB1 - 1;
    const float4* src = reinterpret_cast<const float4*>(embed + (size_t)idx * DIN);
    float4* dst = reinterpret_cast<float4*>(g_xs + ((size_t)t * BB + b) * DIN);
    dst[threadIdx.x] = src[threadIdx.x];   // 128 threads * float4 = 512 floats
}

// ---------------- generic tiled SGEMM: C[m,n] = A[m,:].B[n,:] + bias[n] ----------------
// A: [M,K] row-major, B: [N,K] row-major. remap=1 writes logits in (b,t,v) order.
template <int BM, int BN, int BK, int TM, int TN>
__global__ void sgemm_tn(const float* __restrict__ A, const float* __restrict__ Bm,
                         const float* __restrict__ bias, float* __restrict__ C,
                         int M, int N, int K, int remap) {
    __shared__ float As[BK][BM];
    __shared__ float Bs[BK][BN];
    const int tid = threadIdx.x;
    const int m0 = blockIdx.y * BM;
    const int n0 = blockIdx.x * BN;
    const int NTX = BN / TN;                 // threads in n
    const int tx = tid % NTX;
    const int ty = tid / NTX;

    float acc[TM][TN];
#pragma unroll
    for (int i = 0; i < TM; i++)
#pragma unroll
        for (int j = 0; j < TN; j++) acc[i][j] = 0.f;

    const int KQ = BK / 4;
    for (int kt = 0; kt < K; kt += BK) {
        // load A tile (BM x BK), store transposed As[k][m]
        for (int q = tid; q < BM * KQ; q += blockDim.x) {
            int row = q / KQ;
            int kq = (q % KQ) * 4;
            float4 v = make_float4(0.f, 0.f, 0.f, 0.f);
            int gm = m0 + row;
            if (gm < M) v = *reinterpret_cast<const float4*>(A + (size_t)gm * K + kt + kq);
            As[kq + 0][row] = v.x; As[kq + 1][row] = v.y;
            As[kq + 2][row] = v.z; As[kq + 3][row] = v.w;
        }
        // load B tile (BN x BK), store transposed Bs[k][n]
        for (int q = tid; q < BN * KQ; q += blockDim.x) {
            int row = q / KQ;
            int kq = (q % KQ) * 4;
            float4 v = make_float4(0.f, 0.f, 0.f, 0.f);
            int gn = n0 + row;
            if (gn < N) v = *reinterpret_cast<const float4*>(Bm + (size_t)gn * K + kt + kq);
            Bs[kq + 0][row] = v.x; Bs[kq + 1][row] = v.y;
            Bs[kq + 2][row] = v.z; Bs[kq + 3][row] = v.w;
        }
        __syncthreads();
#pragma unroll
        for (int k = 0; k < BK; k++) {
            float a[TM], b[TN];
#pragma unroll
            for (int i = 0; i < TM; i++) a[i] = As[k][ty * TM + i];
#pragma unroll
            for (int j = 0; j < TN; j++) b[j] = Bs[k][tx * TN + j];
#pragma unroll
            for (int i = 0; i < TM; i++)
#pragma unroll
                for (int j = 0; j < TN; j++) acc[i][j] = fmaf(a[i], b[j], acc[i][j]);
        }
        __syncthreads();
    }

#pragma unroll
    for (int i = 0; i < TM; i++) {
        int m = m0 + ty * TM + i;
        if (m >= M) continue;
        size_t base = remap ? ((size_t)((m & 63) * TT + (m >> 6))) * (size_t)N
                            : (size_t)m * (size_t)N;
#pragma unroll
        for (int j = 0; j < TN; j++) {
            int n = n0 + tx * TN + j;
            if (n < N) C[base + n] = acc[i][j] + (bias ? bias[n] : 0.f);
        }
    }
}

// ---------------- recurrent GEMM: gp[kz] = h(64x512-slice) @ W_hh^T ----------------
// BM=64 (full M), BN=32, BK=16, TM=4, TN=2, 256 threads. grid=(64, KSPLIT)
__global__ void step_gemm(const float* __restrict__ Whh) {
    __shared__ float As[16][64];
    __shared__ float Bs[16][32];
    const int tid = threadIdx.x;
    const int n0 = blockIdx.x * 32;
    const int kz = blockIdx.y;
    const int kbeg = kz * (DR / KSPLIT);     // 128 per split
    const int tx = tid & 15;                 // n group
    const int ty = tid >> 4;                 // m group
    float acc[4][2] = {};

    for (int kt = 0; kt < DR / KSPLIT; kt += 16) {
        {
            int row = tid >> 2, kq = (tid & 3) << 2;
            float4 v = *reinterpret_cast<const float4*>(g_h + row * DR + kbeg + kt + kq);
            As[kq + 0][row] = v.x; As[kq + 1][row] = v.y;
            As[kq + 2][row] = v.z; As[kq + 3][row] = v.w;
        }
        if (tid < 128) {
            int row = tid >> 2, kq = (tid & 3) << 2;
            float4 v = *reinterpret_cast<const float4*>(Whh + (size_t)(n0 + row) * DR + kbeg + kt + kq);
            Bs[kq + 0][row] = v.x; Bs[kq + 1][row] = v.y;
            Bs[kq + 2][row] = v.z; Bs[kq + 3][row] = v.w;
        }
        __syncthreads();
#pragma unroll
        for (int k = 0; k < 16; k++) {
            float a0 = As[k][ty * 4 + 0], a1 = As[k][ty * 4 + 1];
            float a2 = As[k][ty * 4 + 2], a3 = As[k][ty * 4 + 3];
            float b0 = Bs[k][tx * 2 + 0], b1 = Bs[k][tx * 2 + 1];
            acc[0][0] = fmaf(a0, b0, acc[0][0]); acc[0][1] = fmaf(a0, b1, acc[0][1]);
            acc[1][0] = fmaf(a1, b0, acc[1][0]); acc[1][1] = fmaf(a1, b1, acc[1][1]);
            acc[2][0] = fmaf(a2, b0, acc[2][0]); acc[2][1] = fmaf(a2, b1, acc[2][1]);
            acc[3][0] = fmaf(a3, b0, acc[3][0]); acc[3][1] = fmaf(a3, b1, acc[3][1]);
        }
        __syncthreads();
    }
    float* gp = g_gp + (size_t)kz * BB * G4;
#pragma unroll
    for (int i = 0; i < 4; i++)
#pragma unroll
        for (int j = 0; j < 2; j++)
            gp[(ty * 4 + i) * G4 + n0 + tx * 2 + j] = acc[i][j];
}

// ---------------- LSTM elementwise: sum partials + gates_x, update h/c, store hs ----------------
__device__ __forceinline__ float sigmoidf_(float x) { return 1.f / (1.f + __expf(-x)); }

__global__ void lstm_ew(int t) {
    int id = blockIdx.x * blockDim.x + threadIdx.x;   // 0..32767
    int b = id >> 9, r = id & 511;
    const float* gx = g_gx + ((size_t)t * BB + b) * G4;
    float vi = gx[r], vf = gx[512 + r], vg = gx[1024 + r], vo = gx[1536 + r];
#pragma unroll
    for (int kz = 0; kz < KSPLIT; kz++) {
        const float* gp = g_gp + ((size_t)kz * BB + b) * G4;
        vi += gp[r]; vf += gp[512 + r]; vg += gp[1024 + r]; vo += gp[1536 + r];
    }
    float c = g_c[id];
    float cn = sigmoidf_(vf) * c + sigmoidf_(vi) * tanhf(vg);
    float hn = sigmoidf_(vo) * tanhf(cn);
    g_c[id] = cn;
    g_h[id] = hn;
    g_hs[(size_t)t * BB * DR + id] = hn;
}

// ---------------- log-softmax pass 1: per-row online logsumexp ----------------
__global__ void row_lse(const float* __restrict__ out) {
    int row = blockIdx.x;                      // row = b*TT + t
    const float* p = out + (size_t)row * VOCAB1;
    float m = -INFINITY, s = 0.f;
    for (int v = threadIdx.x; v < VOCAB1; v += blockDim.x) {
        float x = p[v];
        if (x > m) { s = s * __expf(m - x) + 1.f; m = x; }
        else       { s += __expf(x - m); }
    }
#pragma unroll
    for (int o = 16; o > 0; o >>= 1) {
        float m2 = __shfl_xor_sync(0xffffffffu, m, o);
        float s2 = __shfl_xor_sync(0xffffffffu, s, o);
        if (m2 > m) { s = s * __expf(m - m2) + s2; m = m2; }
        else        { s += s2 * __expf(m2 - m); }
    }
    __shared__ float sm[8], ss[8];
    int lane = threadIdx.x & 31, w = threadIdx.x >> 5;
    if (lane == 0) { sm[w] = m; ss[w] = s; }
    __syncthreads();
    if (threadIdx.x == 0) {
        float M = sm[0], S = ss[0];
        for (int i = 1; i < 8; i++) {
            float m2 = sm[i], s2 = ss[i];
            if (m2 > M) { S = S * __expf(M - m2) + s2; M = m2; }
            else        { S += s2 * __expf(m2 - M); }
        }
        g_lse[row] = M + logf(S);
    }
}

// ---------------- log-softmax pass 2: subtract lse ----------------
__global__ void sub_lse(float* __restrict__ out) {
    int row = blockIdx.y;
    int v = blockIdx.x * blockDim.x + threadIdx.x;
    if (v < VOCAB1) out[(size_t)row * VOCAB1 + v] -= g_lse[row];
}

// ---------------- launch ----------------
extern "C" void kernel_launch(void* const* d_in, const int* in_sizes, int n_in,
                              void* d_out, int out_size) {
    const float* img_feat = (const float*)d_in[0];
    const int*   seq      = (const int*)d_in[1];     // int32 (JAX x64 disabled)
    const float* W_img    = (const float*)d_in[2];
    const float* b_img    = (const float*)d_in[3];
    const float* embed    = (const float*)d_in[4];
    const float* W_ih     = (const float*)d_in[5];
    const float* b_ih     = (const float*)d_in[6];
    const float* W_hh     = (const float*)d_in[7];
    const float* b_hh     = (const float*)d_in[8];
    const float* W_logit  = (const float*)d_in[9];
    const float* b_logit  = (const float*)d_in[10];
    float* out = (float*)d_out;

    float *xs, *gx, *hs, *bias2;
    cudaGetSymbolAddress((void**)&xs,    g_xs);
    cudaGetSymbolAddress((void**)&gx,    g_gx);
    cudaGetSymbolAddress((void**)&hs,    g_hs);
    cudaGetSymbolAddress((void**)&bias2, g_bias2);

    // init h/c, bias2
    init_k<<<128, 256>>>(b_ih, b_hh);
    // embedding rows for t=1..19
    gather_embed<<<dim3(19, 64), 128>>>(seq, embed);
    // x0 = img_feat @ W_img^T + b_img  -> xs[0]
    sgemm_tn<128, 64, 16, 8, 4><<<dim3(8, 1), 256>>>(img_feat, W_img, b_img, xs,
                                                     BB, DIN, DF, 0);
    // gates_x = xs @ W_ih^T + (b_ih + b_hh)
    sgemm_tn<128, 64, 16, 8, 4><<<dim3(G4 / 64, (TT * BB) / 128), 256>>>(
        xs, W_ih, bias2, gx, TT * BB, G4, DIN, 0);

    // sequential LSTM
    for (int t = 0; t < TT; t++) {
        step_gemm<<<dim3(G4 / 32, KSPLIT), 256>>>(W_hh);
        lstm_ew<<<(BB * DR) / 256, 256>>>(t);
    }

    // logits = hs @ W_logit^T + b_logit, written as out[b][t][v]
    sgemm_tn<128, 64, 16, 8, 4><<<dim3((VOCAB1 + 63) / 64, (TT * BB) / 128), 256>>>(
        hs, W_logit, b_logit, out, TT * BB, VOCAB1, DIN, 1);

    // log-softmax
    row_lse<<<BB * TT, 256>>>(out);
    sub_lse<<<dim3((VOCAB1 + 255) / 256, BB * TT), 256>>>(out);
}

// round 5
// speedup vs baseline: 1.7780x; 1.7780x over previous
#include <cuda_runtime.h>
#include <cuda_bf16.h>
#include <math.h>
#include <stdint.h>

#define VOCAB1 32001
#define DIN 512
#define DR  512
#define DF  2048
#define BB  64
#define TT  20
#define G4  2048   // 4*DR
#define KSPLIT 4

// ================= device scratch =================
__device__ __align__(16) float g_xs[TT * BB * DIN];
__device__ __align__(16) float g_gx[(size_t)TT * BB * G4];
__device__ __align__(16) float g_h[BB * DR];
__device__ __align__(16) float g_c[BB * DR];
__device__ __align__(16) __nv_bfloat16 g_hsb[TT * BB * DR];        // hs in bf16
__device__ __align__(16) __nv_bfloat16 g_wlb[(size_t)VOCAB1 * DR]; // W_logit bf16
__device__ __align__(16) float g_gp[KSPLIT * BB * G4];
__device__ __align__(16) float g_bias2[G4];
__device__ __align__(16) float g_lse[BB * TT];

// ================= small kernels =================
__global__ void init_k(const float* __restrict__ b_ih, const float* __restrict__ b_hh) {
    int id = blockIdx.x * blockDim.x + threadIdx.x;
    if (id < BB * DR) { g_h[id] = 0.f; g_c[id] = 0.f; }
    if (id < G4) g_bias2[id] = b_ih[id] + b_hh[id];
}

__global__ void gather_embed(const int* __restrict__ seq, const float* __restrict__ embed) {
    int t = 1 + blockIdx.x, b = blockIdx.y;
    int idx = seq[b * TT + t];
    if (idx < 0) idx = 0;
    if (idx > VOCAB1 - 1) idx = VOCAB1 - 1;
    const float4* src = reinterpret_cast<const float4*>(embed + (size_t)idx * DIN);
    float4* dst = reinterpret_cast<float4*>(g_xs + ((size_t)t * BB + b) * DIN);
    dst[threadIdx.x] = src[threadIdx.x];
}

__global__ void conv_wl(const float* __restrict__ w) {
    size_t i = ((size_t)blockIdx.x * blockDim.x + threadIdx.x) * 4;
    if (i + 3 < (size_t)VOCAB1 * DR) {
        float4 v = *reinterpret_cast<const float4*>(w + i);
        __nv_bfloat162 p0 = __floats2bfloat162_rn(v.x, v.y);
        __nv_bfloat162 p1 = __floats2bfloat162_rn(v.z, v.w);
        uint2 u;
        u.x = *reinterpret_cast<uint32_t*>(&p0);
        u.y = *reinterpret_cast<uint32_t*>(&p1);
        *reinterpret_cast<uint2*>(&g_wlb[i]) = u;
    }
}

// ================= fp32 SGEMM (x0, gates_x) =================
template <int BM, int BN, int BK, int TM, int TN>
__global__ void sgemm_tn(const float* __restrict__ A, const float* __restrict__ Bm,
                         const float* __restrict__ bias, float* __restrict__ C,
                         int M, int N, int K) {
    __shared__ float As[BK][BM];
    __shared__ float Bs[BK][BN];
    const int tid = threadIdx.x;
    const int m0 = blockIdx.y * BM;
    const int n0 = blockIdx.x * BN;
    const int NTX = BN / TN;
    const int tx = tid % NTX;
    const int ty = tid / NTX;
    float acc[TM][TN];
#pragma unroll
    for (int i = 0; i < TM; i++)
#pragma unroll
        for (int j = 0; j < TN; j++) acc[i][j] = 0.f;
    const int KQ = BK / 4;
    for (int kt = 0; kt < K; kt += BK) {
        for (int q = tid; q < BM * KQ; q += blockDim.x) {
            int row = q / KQ, kq = (q % KQ) * 4;
            float4 v = make_float4(0.f, 0.f, 0.f, 0.f);
            int gm = m0 + row;
            if (gm < M) v = *reinterpret_cast<const float4*>(A + (size_t)gm * K + kt + kq);
            As[kq + 0][row] = v.x; As[kq + 1][row] = v.y;
            As[kq + 2][row] = v.z; As[kq + 3][row] = v.w;
        }
        for (int q = tid; q < BN * KQ; q += blockDim.x) {
            int row = q / KQ, kq = (q % KQ) * 4;
            float4 v = make_float4(0.f, 0.f, 0.f, 0.f);
            int gn = n0 + row;
            if (gn < N) v = *reinterpret_cast<const float4*>(Bm + (size_t)gn * K + kt + kq);
            Bs[kq + 0][row] = v.x; Bs[kq + 1][row] = v.y;
            Bs[kq + 2][row] = v.z; Bs[kq + 3][row] = v.w;
        }
        __syncthreads();
#pragma unroll
        for (int k = 0; k < BK; k++) {
            float a[TM], b[TN];
#pragma unroll
            for (int i = 0; i < TM; i++) a[i] = As[k][ty * TM + i];
#pragma unroll
            for (int j = 0; j < TN; j++) b[j] = Bs[k][tx * TN + j];
#pragma unroll
            for (int i = 0; i < TM; i++)
#pragma unroll
                for (int j = 0; j < TN; j++) acc[i][j] = fmaf(a[i], b[j], acc[i][j]);
        }
        __syncthreads();
    }
#pragma unroll
    for (int i = 0; i < TM; i++) {
        int m = m0 + ty * TM + i;
        if (m >= M) continue;
#pragma unroll
        for (int j = 0; j < TN; j++) {
            int n = n0 + tx * TN + j;
            if (n < N) C[(size_t)m * N + n] = acc[i][j] + (bias ? bias[n] : 0.f);
        }
    }
}

// ================= recurrent GEMM + LSTM elementwise =================
__global__ void step_gemm(const float* __restrict__ Whh) {
    __shared__ float As[16][64];
    __shared__ float Bs[16][32];
    const int tid = threadIdx.x;
    const int n0 = blockIdx.x * 32;
    const int kz = blockIdx.y;
    const int kbeg = kz * (DR / KSPLIT);
    const int tx = tid & 15, ty = tid >> 4;
    float acc[4][2] = {};
    for (int kt = 0; kt < DR / KSPLIT; kt += 16) {
        {
            int row = tid >> 2, kq = (tid & 3) << 2;
            float4 v = *reinterpret_cast<const float4*>(g_h + row * DR + kbeg + kt + kq);
            As[kq + 0][row] = v.x; As[kq + 1][row] = v.y;
            As[kq + 2][row] = v.z; As[kq + 3][row] = v.w;
        }
        if (tid < 128) {
            int row = tid >> 2, kq = (tid & 3) << 2;
            float4 v = *reinterpret_cast<const float4*>(Whh + (size_t)(n0 + row) * DR + kbeg + kt + kq);
            Bs[kq + 0][row] = v.x; Bs[kq + 1][row] = v.y;
            Bs[kq + 2][row] = v.z; Bs[kq + 3][row] = v.w;
        }
        __syncthreads();
#pragma unroll
        for (int k = 0; k < 16; k++) {
            float a0 = As[k][ty * 4 + 0], a1 = As[k][ty * 4 + 1];
            float a2 = As[k][ty * 4 + 2], a3 = As[k][ty * 4 + 3];
            float b0 = Bs[k][tx * 2 + 0], b1 = Bs[k][tx * 2 + 1];
            acc[0][0] = fmaf(a0, b0, acc[0][0]); acc[0][1] = fmaf(a0, b1, acc[0][1]);
            acc[1][0] = fmaf(a1, b0, acc[1][0]); acc[1][1] = fmaf(a1, b1, acc[1][1]);
            acc[2][0] = fmaf(a2, b0, acc[2][0]); acc[2][1] = fmaf(a2, b1, acc[2][1]);
            acc[3][0] = fmaf(a3, b0, acc[3][0]); acc[3][1] = fmaf(a3, b1, acc[3][1]);
        }
        __syncthreads();
    }
    float* gp = g_gp + (size_t)kz * BB * G4;
#pragma unroll
    for (int i = 0; i < 4; i++)
#pragma unroll
        for (int j = 0; j < 2; j++)
            gp[(ty * 4 + i) * G4 + n0 + tx * 2 + j] = acc[i][j];
}

__device__ __forceinline__ float sigmoidf_(float x) { return 1.f / (1.f + __expf(-x)); }

__global__ void lstm_ew(int t) {
    int id = blockIdx.x * blockDim.x + threadIdx.x;
    int b = id >> 9, r = id & 511;
    const float* gx = g_gx + ((size_t)t * BB + b) * G4;
    float vi = gx[r], vf = gx[512 + r], vg = gx[1024 + r], vo = gx[1536 + r];
#pragma unroll
    for (int kz = 0; kz < KSPLIT; kz++) {
        const float* gp = g_gp + ((size_t)kz * BB + b) * G4;
        vi += gp[r]; vf += gp[512 + r]; vg += gp[1024 + r]; vo += gp[1536 + r];
    }
    float c = g_c[id];
    float cn = sigmoidf_(vf) * c + sigmoidf_(vi) * tanhf(vg);
    float hn = sigmoidf_(vo) * tanhf(cn);
    g_c[id] = cn;
    g_h[id] = hn;
    g_hsb[(size_t)t * BB * DR + id] = __float2bfloat16(hn);
}

// ================= bf16 logits GEMM via mma.sync (m16n8k16, sm_100-safe) =================
// CTA tile 128x128, K in 32-chunks, 8 warps (2x4), warp tile 64x32.
// SMEM rows padded to 40 bf16 (conflict-free lds for fragment pattern).
#define SP 40
#define LG_DSMEM (128 * 132 * 4)   // 67584; mainloop uses first 20480 bytes

__device__ __forceinline__ void mma16816(float* d, uint32_t a0, uint32_t a1,
                                         uint32_t a2, uint32_t a3,
                                         uint32_t b0, uint32_t b1) {
    asm volatile(
        "mma.sync.aligned.m16n8k16.row.col.f32.bf16.bf16.f32 "
        "{%0,%1,%2,%3}, {%4,%5,%6,%7}, {%8,%9}, {%0,%1,%2,%3};"
        : "+f"(d[0]), "+f"(d[1]), "+f"(d[2]), "+f"(d[3])
        : "r"(a0), "r"(a1), "r"(a2), "r"(a3), "r"(b0), "r"(b1));
}

__global__ void __launch_bounds__(256) logits_mma(const __nv_bfloat16* __restrict__ hsb,
                                                  const __nv_bfloat16* __restrict__ wlb,
                                                  const float* __restrict__ b_logit,
                                                  float* __restrict__ out) {
    extern __shared__ char smem[];
    __nv_bfloat16* Asp = reinterpret_cast<__nv_bfloat16*>(smem);            // 128*SP
    __nv_bfloat16* Bsp = reinterpret_cast<__nv_bfloat16*>(smem + 10240);    // 128*SP
    const int tid = threadIdx.x, wid = tid >> 5, lid = tid & 31;
    const int gid = lid >> 2, tig = lid & 3;
    const int n0 = blockIdx.x * 128;
    const int m0 = blockIdx.y * 128;
    const int wm = (wid >> 2) * 64;   // warp m offset (0 or 64)
    const int wn = (wid & 3) * 32;    // warp n offset

    float acc[4][4][4];
#pragma unroll
    for (int i = 0; i < 4; i++)
#pragma unroll
        for (int j = 0; j < 4; j++)
#pragma unroll
            for (int r = 0; r < 4; r++) acc[i][j][r] = 0.f;

    // load-index mapping: li in [0,512): row=li>>2, group=li&3 (16B each)
    const int li0 = tid * 2, li1 = tid * 2 + 1;
    const int ar0 = li0 >> 2, ag0 = li0 & 3, ar1 = li1 >> 2, ag1 = li1 & 3;
    int bn0 = n0 + ar0; if (bn0 > VOCAB1 - 1) bn0 = VOCAB1 - 1;
    int bn1 = n0 + ar1; if (bn1 > VOCAB1 - 1) bn1 = VOCAB1 - 1;

    uint4 pa0, pa1, pb0, pb1;
    // prefetch k-chunk 0
    pa0 = *reinterpret_cast<const uint4*>(hsb + (size_t)(m0 + ar0) * DIN + ag0 * 8);
    pa1 = *reinterpret_cast<const uint4*>(hsb + (size_t)(m0 + ar1) * DIN + ag1 * 8);
    pb0 = *reinterpret_cast<const uint4*>(wlb + (size_t)bn0 * DIN + ag0 * 8);
    pb1 = *reinterpret_cast<const uint4*>(wlb + (size_t)bn1 * DIN + ag1 * 8);

    for (int kt = 0; kt < 16; kt++) {
        __syncthreads();   // previous compute done before overwrite
        *reinterpret_cast<uint4*>(Asp + ar0 * SP + ag0 * 8) = pa0;
        *reinterpret_cast<uint4*>(Asp + ar1 * SP + ag1 * 8) = pa1;
        *reinterpret_cast<uint4*>(Bsp + ar0 * SP + ag0 * 8) = pb0;
        *reinterpret_cast<uint4*>(Bsp + ar1 * SP + ag1 * 8) = pb1;
        __syncthreads();
        if (kt < 15) {
            int k0 = (kt + 1) * 32;
            pa0 = *reinterpret_cast<const uint4*>(hsb + (size_t)(m0 + ar0) * DIN + k0 + ag0 * 8);
            pa1 = *reinterpret_cast<const uint4*>(hsb + (size_t)(m0 + ar1) * DIN + k0 + ag1 * 8);
            pb0 = *reinterpret_cast<const uint4*>(wlb + (size_t)bn0 * DIN + k0 + ag0 * 8);
            pb1 = *reinterpret_cast<const uint4*>(wlb + (size_t)bn1 * DIN + k0 + ag1 * 8);
        }
#pragma unroll
        for (int ks = 0; ks < 32; ks += 16) {
            uint32_t af[4][4], bf[4][2];
#pragma unroll
            for (int mt = 0; mt < 4; mt++) {
                int r = wm + mt * 16 + gid;
                int k = ks + tig * 2;
                af[mt][0] = *reinterpret_cast<const uint32_t*>(Asp + r * SP + k);
                af[mt][1] = *reinterpret_cast<const uint32_t*>(Asp + (r + 8) * SP + k);
                af[mt][2] = *reinterpret_cast<const uint32_t*>(Asp + r * SP + k + 8);
                af[mt][3] = *reinterpret_cast<const uint32_t*>(Asp + (r + 8) * SP + k + 8);
            }
#pragma unroll
            for (int nt = 0; nt < 4; nt++) {
                int n = wn + nt * 8 + gid;
                int k = ks + tig * 2;
                bf[nt][0] = *reinterpret_cast<const uint32_t*>(Bsp + n * SP + k);
                bf[nt][1] = *reinterpret_cast<const uint32_t*>(Bsp + n * SP + k + 8);
            }
#pragma unroll
            for (int mt = 0; mt < 4; mt++)
#pragma unroll
                for (int nt = 0; nt < 4; nt++)
                    mma16816(acc[mt][nt], af[mt][0], af[mt][1], af[mt][2], af[mt][3],
                             bf[nt][0], bf[nt][1]);
        }
    }

    // epilogue: stage tile (+bias) into smem (stride 132), then coalesced remap writes
    __syncthreads();
    float* stg = reinterpret_cast<float*>(smem);
#pragma unroll
    for (int mt = 0; mt < 4; mt++) {
#pragma unroll
        for (int nt = 0; nt < 4; nt++) {
            int r = wm + mt * 16 + gid;
            int c = wn + nt * 8 + tig * 2;
            int n = n0 + c;
            int ncl = (n > VOCAB1 - 1) ? VOCAB1 - 1 : n;
            int ncl1 = (n + 1 > VOCAB1 - 1) ? VOCAB1 - 1 : n + 1;
            float bv0 = b_logit[ncl], bv1 = b_logit[ncl1];
            stg[r * 132 + c]            = acc[mt][nt][0] + bv0;
            stg[r * 132 + c + 1]        = acc[mt][nt][1] + bv1;
            stg[(r + 8) * 132 + c]      = acc[mt][nt][2] + bv0;
            stg[(r + 8) * 132 + c + 1]  = acc[mt][nt][3] + bv1;
        }
    }
    __syncthreads();
    int nmax = VOCAB1 - n0;
    if (nmax > 128) nmax = 128;
    for (int row = wid; row < 128; row += 8) {
        int m = m0 + row;
        int t = m >> 6, b = m & 63;
        float* op = out + ((size_t)(b * TT + t)) * VOCAB1 + n0;
        for (int c = lid; c < nmax; c += 32) op[c] = stg[row * 132 + c];
    }
}

// ================= log-softmax =================
__global__ void row_lse(const float* __restrict__ out) {
    int row = blockIdx.x;
    const float* p = out + (size_t)row * VOCAB1;
    float m = -INFINITY, s = 0.f;
    for (int v = threadIdx.x; v < VOCAB1; v += blockDim.x) {
        float x = p[v];
        if (x > m) { s = s * __expf(m - x) + 1.f; m = x; }
        else       { s += __expf(x - m); }
    }
#pragma unroll
    for (int o = 16; o > 0; o >>= 1) {
        float m2 = __shfl_xor_sync(0xffffffffu, m, o);
        float s2 = __shfl_xor_sync(0xffffffffu, s, o);
        if (m2 > m) { s = s * __expf(m - m2) + s2; m = m2; }
        else        { s += s2 * __expf(m2 - m); }
    }
    __shared__ float sm[8], ss[8];
    int lane = threadIdx.x & 31, w = threadIdx.x >> 5;
    if (lane == 0) { sm[w] = m; ss[w] = s; }
    __syncthreads();
    if (threadIdx.x == 0) {
        float M = sm[0], S = ss[0];
        for (int i = 1; i < 8; i++) {
            float m2 = sm[i], s2 = ss[i];
            if (m2 > M) { S = S * __expf(M - m2) + s2; M = m2; }
            else        { S += s2 * __expf(m2 - M); }
        }
        g_lse[row] = M + logf(S);
    }
}

__global__ void sub_lse(float* __restrict__ out) {
    int row = blockIdx.y;
    int v = blockIdx.x * blockDim.x + threadIdx.x;
    if (v < VOCAB1) out[(size_t)row * VOCAB1 + v] -= g_lse[row];
}

// ================= launch =================
extern "C" void kernel_launch(void* const* d_in, const int* in_sizes, int n_in,
                              void* d_out, int out_size) {
    const float* img_feat = (const float*)d_in[0];
    const int*   seq      = (const int*)d_in[1];
    const float* W_img    = (const float*)d_in[2];
    const float* b_img    = (const float*)d_in[3];
    const float* embed    = (const float*)d_in[4];
    const float* W_ih     = (const float*)d_in[5];
    const float* b_ih     = (const float*)d_in[6];
    const float* W_hh     = (const float*)d_in[7];
    const float* b_hh     = (const float*)d_in[8];
    const float* W_logit  = (const float*)d_in[9];
    const float* b_logit  = (const float*)d_in[10];
    float* out = (float*)d_out;

    float *xs, *gx, *bias2;
    __nv_bfloat16 *hsb, *wlb;
    cudaGetSymbolAddress((void**)&xs,    g_xs);
    cudaGetSymbolAddress((void**)&gx,    g_gx);
    cudaGetSymbolAddress((void**)&bias2, g_bias2);
    cudaGetSymbolAddress((void**)&hsb,   g_hsb);
    cudaGetSymbolAddress((void**)&wlb,   g_wlb);

    cudaFuncSetAttribute(logits_mma, cudaFuncAttributeMaxDynamicSharedMemorySize, LG_DSMEM);

    init_k<<<128, 256>>>(b_ih, b_hh);
    gather_embed<<<dim3(19, 64), 128>>>(seq, embed);
    conv_wl<<<(VOCAB1 * DR / 4 + 255) / 256, 256>>>(W_logit);

    sgemm_tn<128, 64, 16, 8, 4><<<dim3(8, 1), 256>>>(img_feat, W_img, b_img, xs, BB, DIN, DF);
    sgemm_tn<128, 64, 16, 8, 4><<<dim3(G4 / 64, (TT * BB) / 128), 256>>>(
        xs, W_ih, bias2, gx, TT * BB, G4, DIN);

    for (int t = 0; t < TT; t++) {
        step_gemm<<<dim3(G4 / 32, KSPLIT), 256>>>(W_hh);
        lstm_ew<<<(BB * DR) / 256, 256>>>(t);
    }

    logits_mma<<<dim3((VOCAB1 + 127) / 128, 10), 256, LG_DSMEM>>>(hsb, wlb, b_logit, out);

    row_lse<<<BB * TT, 256>>>(out);
    sub_lse<<<dim3((VOCAB1 + 255) / 256, BB * TT), 256>>>(out);
}

// round 6
// speedup vs baseline: 2.6226x; 1.4750x over previous
#include <cuda_runtime.h>
#include <cuda_bf16.h>
#include <math.h>
#include <stdint.h>

#define VOCAB1 32001
#define DIN 512
#define DR  512
#define DF  2048
#define BB  64
#define TT  20
#define G4  2048
#define KSPLIT 4
#define NBLK_LG 251   // ceil(32001/128)

// ================= device scratch =================
__device__ __align__(16) __nv_bfloat16 g_xsb[TT * BB * DIN];       // xs bf16
__device__ __align__(16) float g_gx[(size_t)TT * BB * G4];
__device__ __align__(16) float g_h[BB * DR];
__device__ __align__(16) float g_c[BB * DR];
__device__ __align__(16) __nv_bfloat16 g_hsb[TT * BB * DR];
__device__ __align__(16) __nv_bfloat16 g_wlb[(size_t)VOCAB1 * DR]; // W_logit bf16
__device__ __align__(16) __nv_bfloat16 g_wib[(size_t)G4 * DIN];    // W_ih bf16
__device__ __align__(16) float g_gp[KSPLIT * BB * G4];
__device__ __align__(16) float g_bias2[G4];
__device__ __align__(16) float g_lse[BB * TT];
__device__ __align__(16) float g_x0p[8 * BB * DIN];                // x0 k-split partials
__device__ __align__(16) float g_pmax[BB * TT * NBLK_LG];
__device__ __align__(16) float g_psum[BB * TT * NBLK_LG];

// ================= small kernels =================
__global__ void init_k(const float* __restrict__ b_ih, const float* __restrict__ b_hh) {
    int id = blockIdx.x * blockDim.x + threadIdx.x;
    if (id < BB * DR) { g_h[id] = 0.f; g_c[id] = 0.f; }
    if (id < G4) g_bias2[id] = b_ih[id] + b_hh[id];
}

__global__ void gather_embed(const int* __restrict__ seq, const float* __restrict__ embed) {
    int t = 1 + blockIdx.x, b = blockIdx.y;
    int idx = seq[b * TT + t];
    if (idx < 0) idx = 0;
    if (idx > VOCAB1 - 1) idx = VOCAB1 - 1;
    float4 v = reinterpret_cast<const float4*>(embed + (size_t)idx * DIN)[threadIdx.x];
    __nv_bfloat162 p0 = __floats2bfloat162_rn(v.x, v.y);
    __nv_bfloat162 p1 = __floats2bfloat162_rn(v.z, v.w);
    uint2 u;
    u.x = *reinterpret_cast<uint32_t*>(&p0);
    u.y = *reinterpret_cast<uint32_t*>(&p1);
    reinterpret_cast<uint2*>(g_xsb + ((size_t)t * BB + b) * DIN)[threadIdx.x] = u;
}

__global__ void conv_bf16(const float* __restrict__ w, __nv_bfloat16* __restrict__ dst, size_t n) {
    size_t i = ((size_t)blockIdx.x * blockDim.x + threadIdx.x) * 4;
    if (i + 3 < n) {
        float4 v = *reinterpret_cast<const float4*>(w + i);
        __nv_bfloat162 p0 = __floats2bfloat162_rn(v.x, v.y);
        __nv_bfloat162 p1 = __floats2bfloat162_rn(v.z, v.w);
        uint2 u;
        u.x = *reinterpret_cast<uint32_t*>(&p0);
        u.y = *reinterpret_cast<uint32_t*>(&p1);
        *reinterpret_cast<uint2*>(&dst[i]) = u;
    }
}

// ================= x0: k-split fp32 GEMM (64x512, K=2048 in 8 chunks) =================
__global__ void x0_ksplit(const float* __restrict__ A, const float* __restrict__ Bm) {
    __shared__ float As[16][64];
    __shared__ float Bs[16][64];
    const int tid = threadIdx.x;
    const int n0 = blockIdx.x * 64;
    const int kb = blockIdx.y;
    const int kbeg = kb * 256;
    const int tx = tid & 15, ty = tid >> 4;   // 16x16 thread grid, TM=4 TN=4
    float acc[4][4] = {};
    for (int kt = 0; kt < 256; kt += 16) {
        {
            int row = tid >> 2, kq = (tid & 3) << 2;
            float4 v = *reinterpret_cast<const float4*>(A + (size_t)row * DF + kbeg + kt + kq);
            As[kq + 0][row] = v.x; As[kq + 1][row] = v.y;
            As[kq + 2][row] = v.z; As[kq + 3][row] = v.w;
        }
        {
            int row = tid >> 2, kq = (tid & 3) << 2;
            float4 v = *reinterpret_cast<const float4*>(Bm + (size_t)(n0 + row) * DF + kbeg + kt + kq);
            Bs[kq + 0][row] = v.x; Bs[kq + 1][row] = v.y;
            Bs[kq + 2][row] = v.z; Bs[kq + 3][row] = v.w;
        }
        __syncthreads();
#pragma unroll
        for (int k = 0; k < 16; k++) {
            float a[4], b[4];
#pragma unroll
            for (int i = 0; i < 4; i++) a[i] = As[k][ty * 4 + i];
#pragma unroll
            for (int j = 0; j < 4; j++) b[j] = Bs[k][tx * 4 + j];
#pragma unroll
            for (int i = 0; i < 4; i++)
#pragma unroll
                for (int j = 0; j < 4; j++) acc[i][j] = fmaf(a[i], b[j], acc[i][j]);
        }
        __syncthreads();
    }
    float* p = g_x0p + (size_t)kb * BB * DIN;
#pragma unroll
    for (int i = 0; i < 4; i++)
#pragma unroll
        for (int j = 0; j < 4; j++)
            p[(ty * 4 + i) * DIN + n0 + tx * 4 + j] = acc[i][j];
}

__global__ void x0_reduce(const float* __restrict__ b_img) {
    int id = blockIdx.x * blockDim.x + threadIdx.x;   // 0..32767
    float s = b_img[id & 511];
#pragma unroll
    for (int kb = 0; kb < 8; kb++) s += g_x0p[kb * BB * DIN + id];
    g_xsb[id] = __float2bfloat16(s);   // t=0 slice
}

// ================= recurrent GEMM + LSTM elementwise =================
__global__ void step_gemm(const float* __restrict__ Whh) {
    __shared__ float As[16][64];
    __shared__ float Bs[16][32];
    const int tid = threadIdx.x;
    const int n0 = blockIdx.x * 32;
    const int kz = blockIdx.y;
    const int kbeg = kz * (DR / KSPLIT);
    const int tx = tid & 15, ty = tid >> 4;
    float acc[4][2] = {};
    for (int kt = 0; kt < DR / KSPLIT; kt += 16) {
        {
            int row = tid >> 2, kq = (tid & 3) << 2;
            float4 v = *reinterpret_cast<const float4*>(g_h + row * DR + kbeg + kt + kq);
            As[kq + 0][row] = v.x; As[kq + 1][row] = v.y;
            As[kq + 2][row] = v.z; As[kq + 3][row] = v.w;
        }
        if (tid < 128) {
            int row = tid >> 2, kq = (tid & 3) << 2;
            float4 v = *reinterpret_cast<const float4*>(Whh + (size_t)(n0 + row) * DR + kbeg + kt + kq);
            Bs[kq + 0][row] = v.x; Bs[kq + 1][row] = v.y;
            Bs[kq + 2][row] = v.z; Bs[kq + 3][row] = v.w;
        }
        __syncthreads();
#pragma unroll
        for (int k = 0; k < 16; k++) {
            float a0 = As[k][ty * 4 + 0], a1 = As[k][ty * 4 + 1];
            float a2 = As[k][ty * 4 + 2], a3 = As[k][ty * 4 + 3];
            float b0 = Bs[k][tx * 2 + 0], b1 = Bs[k][tx * 2 + 1];
            acc[0][0] = fmaf(a0, b0, acc[0][0]); acc[0][1] = fmaf(a0, b1, acc[0][1]);
            acc[1][0] = fmaf(a1, b0, acc[1][0]); acc[1][1] = fmaf(a1, b1, acc[1][1]);
            acc[2][0] = fmaf(a2, b0, acc[2][0]); acc[2][1] = fmaf(a2, b1, acc[2][1]);
            acc[3][0] = fmaf(a3, b0, acc[3][0]); acc[3][1] = fmaf(a3, b1, acc[3][1]);
        }
        __syncthreads();
    }
    float* gp = g_gp + (size_t)kz * BB * G4;
#pragma unroll
    for (int i = 0; i < 4; i++)
#pragma unroll
        for (int j = 0; j < 2; j++)
            gp[(ty * 4 + i) * G4 + n0 + tx * 2 + j] = acc[i][j];
}

__device__ __forceinline__ float sigmoidf_(float x) { return 1.f / (1.f + __expf(-x)); }

__global__ void lstm_ew(int t) {
    int id = blockIdx.x * blockDim.x + threadIdx.x;
    int b = id >> 9, r = id & 511;
    const float* gx = g_gx + ((size_t)t * BB + b) * G4;
    float vi = gx[r], vf = gx[512 + r], vg = gx[1024 + r], vo = gx[1536 + r];
#pragma unroll
    for (int kz = 0; kz < KSPLIT; kz++) {
        const float* gp = g_gp + ((size_t)kz * BB + b) * G4;
        vi += gp[r]; vf += gp[512 + r]; vg += gp[1024 + r]; vo += gp[1536 + r];
    }
    float c = g_c[id];
    float cn = sigmoidf_(vf) * c + sigmoidf_(vi) * tanhf(vg);
    float hn = sigmoidf_(vo) * tanhf(cn);
    g_c[id] = cn;
    g_h[id] = hn;
    g_hsb[(size_t)t * BB * DR + id] = __float2bfloat16(hn);
}

// ================= generic bf16 mma GEMM (m16n8k16), K=512 =================
// CTA tile 128x128, 8 warps (2x4), warp tile 64x32; SMEM rows padded to 40 bf16.
// REMAP: write rows as out[b*TT+t] with m = t*64+b.  PLSE: emit per-tile max/sumexp.
#define SP 40
#define LG_DSMEM (128 * 132 * 4)

__device__ __forceinline__ void mma16816(float* d, uint32_t a0, uint32_t a1,
                                         uint32_t a2, uint32_t a3,
                                         uint32_t b0, uint32_t b1) {
    asm volatile(
        "mma.sync.aligned.m16n8k16.row.col.f32.bf16.bf16.f32 "
        "{%0,%1,%2,%3}, {%4,%5,%6,%7}, {%8,%9}, {%0,%1,%2,%3};"
        : "+f"(d[0]), "+f"(d[1]), "+f"(d[2]), "+f"(d[3])
        : "r"(a0), "r"(a1), "r"(a2), "r"(a3), "r"(b0), "r"(b1));
}

template <bool REMAP, bool PLSE>
__global__ void __launch_bounds__(256) bmma(const __nv_bfloat16* __restrict__ Abm,
                                            const __nv_bfloat16* __restrict__ Bbm,
                                            const float* __restrict__ bias,
                                            float* __restrict__ C, int NT) {
    extern __shared__ char smem[];
    __nv_bfloat16* Asp = reinterpret_cast<__nv_bfloat16*>(smem);
    __nv_bfloat16* Bsp = reinterpret_cast<__nv_bfloat16*>(smem + 10240);
    const int tid = threadIdx.x, wid = tid >> 5, lid = tid & 31;
    const int gid = lid >> 2, tig = lid & 3;
    const int n0 = blockIdx.x * 128;
    const int m0 = blockIdx.y * 128;
    const int wm = (wid >> 2) * 64;
    const int wn = (wid & 3) * 32;

    float acc[4][4][4];
#pragma unroll
    for (int i = 0; i < 4; i++)
#pragma unroll
        for (int j = 0; j < 4; j++)
#pragma unroll
            for (int r = 0; r < 4; r++) acc[i][j][r] = 0.f;

    const int li0 = tid * 2, li1 = tid * 2 + 1;
    const int ar0 = li0 >> 2, ag0 = li0 & 3, ar1 = li1 >> 2, ag1 = li1 & 3;
    int bn0 = n0 + ar0; if (bn0 > NT - 1) bn0 = NT - 1;
    int bn1 = n0 + ar1; if (bn1 > NT - 1) bn1 = NT - 1;

    uint4 pa0, pa1, pb0, pb1;
    pa0 = *reinterpret_cast<const uint4*>(Abm + (size_t)(m0 + ar0) * DIN + ag0 * 8);
    pa1 = *reinterpret_cast<const uint4*>(Abm + (size_t)(m0 + ar1) * DIN + ag1 * 8);
    pb0 = *reinterpret_cast<const uint4*>(Bbm + (size_t)bn0 * DIN + ag0 * 8);
    pb1 = *reinterpret_cast<const uint4*>(Bbm + (size_t)bn1 * DIN + ag1 * 8);

    for (int kt = 0; kt < 16; kt++) {
        __syncthreads();
        *reinterpret_cast<uint4*>(Asp + ar0 * SP + ag0 * 8) = pa0;
        *reinterpret_cast<uint4*>(Asp + ar1 * SP + ag1 * 8) = pa1;
        *reinterpret_cast<uint4*>(Bsp + ar0 * SP + ag0 * 8) = pb0;
        *reinterpret_cast<uint4*>(Bsp + ar1 * SP + ag1 * 8) = pb1;
        __syncthreads();
        if (kt < 15) {
            int k0 = (kt + 1) * 32;
            pa0 = *reinterpret_cast<const uint4*>(Abm + (size_t)(m0 + ar0) * DIN + k0 + ag0 * 8);
            pa1 = *reinterpret_cast<const uint4*>(Abm + (size_t)(m0 + ar1) * DIN + k0 + ag1 * 8);
            pb0 = *reinterpret_cast<const uint4*>(Bbm + (size_t)bn0 * DIN + k0 + ag0 * 8);
            pb1 = *reinterpret_cast<const uint4*>(Bbm + (size_t)bn1 * DIN + k0 + ag1 * 8);
        }
#pragma unroll
        for (int ks = 0; ks < 32; ks += 16) {
            uint32_t af[4][4], bf[4][2];
#pragma unroll
            for (int mt = 0; mt < 4; mt++) {
                int r = wm + mt * 16 + gid;
                int k = ks + tig * 2;
                af[mt][0] = *reinterpret_cast<const uint32_t*>(Asp + r * SP + k);
                af[mt][1] = *reinterpret_cast<const uint32_t*>(Asp + (r + 8) * SP + k);
                af[mt][2] = *reinterpret_cast<const uint32_t*>(Asp + r * SP + k + 8);
                af[mt][3] = *reinterpret_cast<const uint32_t*>(Asp + (r + 8) * SP + k + 8);
            }
#pragma unroll
            for (int nt = 0; nt < 4; nt++) {
                int n = wn + nt * 8 + gid;
                int k = ks + tig * 2;
                bf[nt][0] = *reinterpret_cast<const uint32_t*>(Bsp + n * SP + k);
                bf[nt][1] = *reinterpret_cast<const uint32_t*>(Bsp + n * SP + k + 8);
            }
#pragma unroll
            for (int mt = 0; mt < 4; mt++)
#pragma unroll
                for (int nt = 0; nt < 4; nt++)
                    mma16816(acc[mt][nt], af[mt][0], af[mt][1], af[mt][2], af[mt][3],
                             bf[nt][0], bf[nt][1]);
        }
    }

    __syncthreads();
    float* stg = reinterpret_cast<float*>(smem);
#pragma unroll
    for (int mt = 0; mt < 4; mt++) {
#pragma unroll
        for (int nt = 0; nt < 4; nt++) {
            int r = wm + mt * 16 + gid;
            int c = wn + nt * 8 + tig * 2;
            int n = n0 + c;
            int ncl = (n > NT - 1) ? NT - 1 : n;
            int ncl1 = (n + 1 > NT - 1) ? NT - 1 : n + 1;
            float bv0 = bias[ncl], bv1 = bias[ncl1];
            stg[r * 132 + c]           = acc[mt][nt][0] + bv0;
            stg[r * 132 + c + 1]       = acc[mt][nt][1] + bv1;
            stg[(r + 8) * 132 + c]     = acc[mt][nt][2] + bv0;
            stg[(r + 8) * 132 + c + 1] = acc[mt][nt][3] + bv1;
        }
    }
    __syncthreads();
    int nmax = NT - n0;
    if (nmax > 128) nmax = 128;
    for (int row = wid; row < 128; row += 8) {
        int m = m0 + row;
        int r_out;
        float* op;
        if (REMAP) {
            int t = m >> 6, b = m & 63;
            r_out = b * TT + t;
            op = C + (size_t)r_out * NT + n0;
        } else {
            r_out = m;
            op = C + (size_t)m * NT + n0;
        }
        float v0 = -INFINITY, v1 = -INFINITY, v2 = -INFINITY, v3 = -INFINITY;
        int c0 = lid, c1 = lid + 32, c2 = lid + 64, c3 = lid + 96;
        if (c0 < nmax) { v0 = stg[row * 132 + c0]; op[c0] = v0; }
        if (c1 < nmax) { v1 = stg[row * 132 + c1]; op[c1] = v1; }
        if (c2 < nmax) { v2 = stg[row * 132 + c2]; op[c2] = v2; }
        if (c3 < nmax) { v3 = stg[row * 132 + c3]; op[c3] = v3; }
        if (PLSE) {
            float mx = fmaxf(fmaxf(v0, v1), fmaxf(v2, v3));
#pragma unroll
            for (int o = 16; o > 0; o >>= 1)
                mx = fmaxf(mx, __shfl_xor_sync(0xffffffffu, mx, o));
            float s = 0.f;
            if (c0 < nmax) s += __expf(v0 - mx);
            if (c1 < nmax) s += __expf(v1 - mx);
            if (c2 < nmax) s += __expf(v2 - mx);
            if (c3 < nmax) s += __expf(v3 - mx);
#pragma unroll
            for (int o = 16; o > 0; o >>= 1)
                s += __shfl_xor_sync(0xffffffffu, s, o);
            if (lid == 0) {
                g_pmax[(size_t)r_out * NBLK_LG + blockIdx.x] = mx;
                g_psum[(size_t)r_out * NBLK_LG + blockIdx.x] = s;
            }
        }
    }
}

// ================= lse reduce + subtract =================
__global__ void lse_reduce() {
    int row = blockIdx.x * 8 + (threadIdx.x >> 5);
    int lid = threadIdx.x & 31;
    float m = -INFINITY, s = 0.f;
    for (int i = lid; i < NBLK_LG; i += 32) {
        float m2 = g_pmax[(size_t)row * NBLK_LG + i];
        float s2 = g_psum[(size_t)row * NBLK_LG + i];
        if (m2 > m) { s = s * __expf(m - m2) + s2; m = m2; }
        else        { s += s2 * __expf(m2 - m); }
    }
#pragma unroll
    for (int o = 16; o > 0; o >>= 1) {
        float m2 = __shfl_xor_sync(0xffffffffu, m, o);
        float s2 = __shfl_xor_sync(0xffffffffu, s, o);
        if (m2 > m) { s = s * __expf(m - m2) + s2; m = m2; }
        else        { s += s2 * __expf(m2 - m); }
    }
    if (lid == 0) g_lse[row] = m + logf(s);
}

__global__ void sub_lse(float* __restrict__ out) {
    int row = blockIdx.y;
    int v = blockIdx.x * blockDim.x + threadIdx.x;
    if (v < VOCAB1) out[(size_t)row * VOCAB1 + v] -= g_lse[row];
}

// ================= launch =================
extern "C" void kernel_launch(void* const* d_in, const int* in_sizes, int n_in,
                              void* d_out, int out_size) {
    const float* img_feat = (const float*)d_in[0];
    const int*   seq      = (const int*)d_in[1];
    const float* W_img    = (const float*)d_in[2];
    const float* b_img    = (const float*)d_in[3];
    const float* embed    = (const float*)d_in[4];
    const float* W_ih     = (const float*)d_in[5];
    const float* b_ih     = (const float*)d_in[6];
    const float* W_hh     = (const float*)d_in[7];
    const float* b_hh     = (const float*)d_in[8];
    const float* W_logit  = (const float*)d_in[9];
    const float* b_logit  = (const float*)d_in[10];
    float* out = (float*)d_out;

    float *gx, *bias2;
    __nv_bfloat16 *xsb, *hsb, *wlb, *wib;
    cudaGetSymbolAddress((void**)&gx,    g_gx);
    cudaGetSymbolAddress((void**)&bias2, g_bias2);
    cudaGetSymbolAddress((void**)&xsb,   g_xsb);
    cudaGetSymbolAddress((void**)&hsb,   g_hsb);
    cudaGetSymbolAddress((void**)&wlb,   g_wlb);
    cudaGetSymbolAddress((void**)&wib,   g_wib);

    cudaFuncSetAttribute(bmma<false, false>, cudaFuncAttributeMaxDynamicSharedMemorySize, LG_DSMEM);
    cudaFuncSetAttribute(bmma<true, true>,   cudaFuncAttributeMaxDynamicSharedMemorySize, LG_DSMEM);

    init_k<<<128, 256>>>(b_ih, b_hh);
    gather_embed<<<dim3(19, 64), 128>>>(seq, embed);
    conv_bf16<<<((size_t)VOCAB1 * DR / 4 + 255) / 256, 256>>>(W_logit, wlb, (size_t)VOCAB1 * DR);
    conv_bf16<<<((size_t)G4 * DIN / 4 + 255) / 256, 256>>>(W_ih, wib, (size_t)G4 * DIN);

    // x0 = img_feat @ W_img^T + b_img -> bf16 xs[0]
    x0_ksplit<<<dim3(8, 8), 256>>>(img_feat, W_img);
    x0_reduce<<<(BB * DIN) / 256, 256>>>(b_img);

    // gates_x = xs @ W_ih^T + bias2  (bf16 tensor cores)
    bmma<false, false><<<dim3(16, 10), 256, LG_DSMEM>>>(xsb, wib, bias2, gx, G4);

    for (int t = 0; t < TT; t++) {
        step_gemm<<<dim3(G4 / 32, KSPLIT), 256>>>(W_hh);
        lstm_ew<<<(BB * DR) / 256, 256>>>(t);
    }

    // logits + fused partial-lse
    bmma<true, true><<<dim3(NBLK_LG, 10), 256, LG_DSMEM>>>(hsb, wlb, b_logit, out, VOCAB1);

    lse_reduce<<<BB * TT / 8, 256>>>();
    sub_lse<<<dim3((VOCAB1 + 255) / 256, BB * TT), 256>>>(out);
}

// round 9
// speedup vs baseline: 3.0455x; 1.1612x over previous
#include <cuda_runtime.h>
#include <cuda_bf16.h>
#include <math.h>
#include <stdint.h>

#define VOCAB1 32001
#define VP     32004   // padded logits row stride (even, x2B = multiple of 8)
#define DIN 512
#define DR  512
#define DF  2048
#define BB  64
#define TT  20
#define G4  2048
#define NBLK_LG 251

// ================= device scratch =================
__device__ __align__(16) __nv_bfloat16 g_xsb[TT * BB * DIN];
__device__ __align__(16) float g_gx[(size_t)TT * BB * G4];
__device__ __align__(16) float g_c[BB * DR];
__device__ __align__(16) __nv_bfloat16 g_hb[BB * DR];
__device__ __align__(16) __nv_bfloat16 g_hsb[TT * BB * DR];
__device__ __align__(16) __nv_bfloat16 g_wlb[(size_t)VOCAB1 * DR];
__device__ __align__(16) __nv_bfloat16 g_wib[(size_t)G4 * DIN];
__device__ __align__(16) __nv_bfloat16 g_whb[(size_t)G4 * DR];
__device__ __align__(16) float g_bias2[G4];
__device__ __align__(16) float g_lse[BB * TT];
__device__ __align__(16) float g_x0p[8 * BB * DIN];
__device__ __align__(16) float g_pmax[BB * TT * NBLK_LG];
__device__ __align__(16) float g_psum[BB * TT * NBLK_LG];
__device__ __align__(16) __nv_bfloat16 g_lgb[(size_t)BB * TT * VP];

// ================= small kernels =================
__global__ void init_k(const float* __restrict__ b_ih, const float* __restrict__ b_hh) {
    int id = blockIdx.x * blockDim.x + threadIdx.x;
    if (id < BB * DR) g_c[id] = 0.f;
    if (id < G4) g_bias2[id] = b_ih[id] + b_hh[id];
}

__global__ void gather_embed(const int* __restrict__ seq, const float* __restrict__ embed) {
    int t = 1 + blockIdx.x, b = blockIdx.y;
    int idx = seq[b * TT + t];
    if (idx < 0) idx = 0;
    if (idx > VOCAB1 - 1) idx = VOCAB1 - 1;
    float4 v = reinterpret_cast<const float4*>(embed + (size_t)idx * DIN)[threadIdx.x];
    __nv_bfloat162 p0 = __floats2bfloat162_rn(v.x, v.y);
    __nv_bfloat162 p1 = __floats2bfloat162_rn(v.z, v.w);
    uint2 u;
    u.x = *reinterpret_cast<uint32_t*>(&p0);
    u.y = *reinterpret_cast<uint32_t*>(&p1);
    reinterpret_cast<uint2*>(g_xsb + ((size_t)t * BB + b) * DIN)[threadIdx.x] = u;
}

__global__ void conv_bf16(const float* __restrict__ w, __nv_bfloat16* __restrict__ dst, size_t n) {
    size_t i = ((size_t)blockIdx.x * blockDim.x + threadIdx.x) * 4;
    if (i + 3 < n) {
        float4 v = *reinterpret_cast<const float4*>(w + i);
        __nv_bfloat162 p0 = __floats2bfloat162_rn(v.x, v.y);
        __nv_bfloat162 p1 = __floats2bfloat162_rn(v.z, v.w);
        uint2 u;
        u.x = *reinterpret_cast<uint32_t*>(&p0);
        u.y = *reinterpret_cast<uint32_t*>(&p1);
        *reinterpret_cast<uint2*>(&dst[i]) = u;
    }
}

// ================= x0: k-split fp32 GEMM =================
__global__ void x0_ksplit(const float* __restrict__ A, const float* __restrict__ Bm) {
    __shared__ float As[16][64];
    __shared__ float Bs[16][64];
    const int tid = threadIdx.x;
    const int n0 = blockIdx.x * 64;
    const int kbeg = blockIdx.y * 256;
    const int tx = tid & 15, ty = tid >> 4;
    float acc[4][4] = {};
    for (int kt = 0; kt < 256; kt += 16) {
        {
            int row = tid >> 2, kq = (tid & 3) << 2;
            float4 v = *reinterpret_cast<const float4*>(A + (size_t)row * DF + kbeg + kt + kq);
            As[kq + 0][row] = v.x; As[kq + 1][row] = v.y;
            As[kq + 2][row] = v.z; As[kq + 3][row] = v.w;
        }
        {
            int row = tid >> 2, kq = (tid & 3) << 2;
            float4 v = *reinterpret_cast<const float4*>(Bm + (size_t)(n0 + row) * DF + kbeg + kt + kq);
            Bs[kq + 0][row] = v.x; Bs[kq + 1][row] = v.y;
            Bs[kq + 2][row] = v.z; Bs[kq + 3][row] = v.w;
        }
        __syncthreads();
#pragma unroll
        for (int k = 0; k < 16; k++) {
            float a[4], b[4];
#pragma unroll
            for (int i = 0; i < 4; i++) a[i] = As[k][ty * 4 + i];
#pragma unroll
            for (int j = 0; j < 4; j++) b[j] = Bs[k][tx * 4 + j];
#pragma unroll
            for (int i = 0; i < 4; i++)
#pragma unroll
                for (int j = 0; j < 4; j++) acc[i][j] = fmaf(a[i], b[j], acc[i][j]);
        }
        __syncthreads();
    }
    float* p = g_x0p + (size_t)blockIdx.y * BB * DIN;
#pragma unroll
    for (int i = 0; i < 4; i++)
#pragma unroll
        for (int j = 0; j < 4; j++)
            p[(ty * 4 + i) * DIN + n0 + tx * 4 + j] = acc[i][j];
}

__global__ void x0_reduce(const float* __restrict__ b_img) {
    int id = blockIdx.x * blockDim.x + threadIdx.x;
    float s = b_img[id & 511];
#pragma unroll
    for (int kb = 0; kb < 8; kb++) s += g_x0p[kb * BB * DIN + id];
    g_xsb[id] = __float2bfloat16(s);
}

// ================= mma primitive =================
__device__ __forceinline__ void mma16816(float* d, uint32_t a0, uint32_t a1,
                                         uint32_t a2, uint32_t a3,
                                         uint32_t b0, uint32_t b1) {
    asm volatile(
        "mma.sync.aligned.m16n8k16.row.col.f32.bf16.bf16.f32 "
        "{%0,%1,%2,%3}, {%4,%5,%6,%7}, {%8,%9}, {%0,%1,%2,%3};"
        : "+f"(d[0]), "+f"(d[1]), "+f"(d[2]), "+f"(d[3])
        : "r"(a0), "r"(a1), "r"(a2), "r"(a3), "r"(b0), "r"(b1));
}

__device__ __forceinline__ float sigmoidf_(float x) { return 1.f / (1.f + __expf(-x)); }

// ================= LSTM step kernel (one launch per step) =================
#define HSTR 520
#define ST_SMEM (64 * HSTR * 2 + 32 * HSTR * 2 + 64 * 33 * 4)

__global__ void __launch_bounds__(256) lstm_step(int t) {
    extern __shared__ char smem[];
    __nv_bfloat16* hS = reinterpret_cast<__nv_bfloat16*>(smem);
    __nv_bfloat16* wS = reinterpret_cast<__nv_bfloat16*>(smem + 64 * HSTR * 2);
    float* gS = reinterpret_cast<float*>(smem + 64 * HSTR * 2 + 32 * HSTR * 2);
    const int tid = threadIdx.x, wid = tid >> 5, lid = tid & 31;
    const int gid = lid >> 2, tig = lid & 3;
    const int cta = blockIdx.x;
    const int c0 = cta * 8;

    if (t > 0) {
        {
            const uint4* src = reinterpret_cast<const uint4*>(g_hb);
            for (int q = tid; q < 4096; q += 256) {
                int row = q >> 6, g = q & 63;
                *reinterpret_cast<uint4*>(hS + row * HSTR + g * 8) = src[row * 64 + g];
            }
        }
        {
            for (int q = tid; q < 2048; q += 256) {
                int j = q >> 6, g = q & 63;
                int wr = (j >> 3) * 512 + c0 + (j & 7);
                *reinterpret_cast<uint4*>(wS + j * HSTR + g * 8) =
                    reinterpret_cast<const uint4*>(g_whb + (size_t)wr * DR)[g];
            }
        }
        __syncthreads();
        const int mrow = (wid >> 1) * 16;
        const int ncol = (wid & 1) * 16;
        float acc[2][4] = {};
#pragma unroll 4
        for (int ks = 0; ks < 512; ks += 16) {
            const __nv_bfloat16* ap = hS + (mrow + gid) * HSTR + ks + tig * 2;
            uint32_t a0 = *reinterpret_cast<const uint32_t*>(ap);
            uint32_t a1 = *reinterpret_cast<const uint32_t*>(ap + 8 * HSTR);
            uint32_t a2 = *reinterpret_cast<const uint32_t*>(ap + 8);
            uint32_t a3 = *reinterpret_cast<const uint32_t*>(ap + 8 * HSTR + 8);
#pragma unroll
            for (int nt = 0; nt < 2; nt++) {
                const __nv_bfloat16* bp = wS + (ncol + nt * 8 + gid) * HSTR + ks + tig * 2;
                uint32_t b0 = *reinterpret_cast<const uint32_t*>(bp);
                uint32_t b1 = *reinterpret_cast<const uint32_t*>(bp + 8);
                mma16816(acc[nt], a0, a1, a2, a3, b0, b1);
            }
        }
#pragma unroll
        for (int nt = 0; nt < 2; nt++) {
            int r0 = mrow + gid;
            int c = ncol + nt * 8 + tig * 2;
            gS[r0 * 33 + c]           = acc[nt][0];
            gS[r0 * 33 + c + 1]       = acc[nt][1];
            gS[(r0 + 8) * 33 + c]     = acc[nt][2];
            gS[(r0 + 8) * 33 + c + 1] = acc[nt][3];
        }
        __syncthreads();
    }

#pragma unroll
    for (int e = tid; e < 512; e += 256) {
        int b = e >> 3, jl = e & 7;
        int r = c0 + jl;
        const float* gxp = g_gx + ((size_t)t * BB + b) * G4;
        float gi = gxp[r], gf = gxp[512 + r], gg = gxp[1024 + r], go = gxp[1536 + r];
        if (t > 0) {
            gi += gS[b * 33 + jl];
            gf += gS[b * 33 + 8 + jl];
            gg += gS[b * 33 + 16 + jl];
            go += gS[b * 33 + 24 + jl];
        }
        int id = b * DR + r;
        float c = (t > 0) ? g_c[id] : 0.f;
        float cn = sigmoidf_(gf) * c + sigmoidf_(gi) * tanhf(gg);
        float hn = sigmoidf_(go) * tanhf(cn);
        g_c[id] = cn;
        __nv_bfloat16 hb = __float2bfloat16(hn);
        g_hb[id] = hb;
        g_hsb[(size_t)t * BB * DR + id] = hb;
    }
}

// ================= generic bf16 mma GEMM (m16n8k16), K=512 =================
#define SP 40
#define LG_DSMEM (128 * 132 * 4)

template <bool REMAP, bool PLSE, bool OBF>
__global__ void __launch_bounds__(256) bmma(const __nv_bfloat16* __restrict__ Abm,
                                            const __nv_bfloat16* __restrict__ Bbm,
                                            const float* __restrict__ bias,
                                            void* __restrict__ Cp, int NT, int ldc) {
    extern __shared__ char smem[];
    __nv_bfloat16* Asp = reinterpret_cast<__nv_bfloat16*>(smem);
    __nv_bfloat16* Bsp = reinterpret_cast<__nv_bfloat16*>(smem + 10240);
    const int tid = threadIdx.x, wid = tid >> 5, lid = tid & 31;
    const int gid = lid >> 2, tig = lid & 3;
    const int n0 = blockIdx.x * 128;
    const int m0 = blockIdx.y * 128;
    const int wm = (wid >> 2) * 64;
    const int wn = (wid & 3) * 32;

    float acc[4][4][4];
#pragma unroll
    for (int i = 0; i < 4; i++)
#pragma unroll
        for (int j = 0; j < 4; j++)
#pragma unroll
            for (int r = 0; r < 4; r++) acc[i][j][r] = 0.f;

    const int li0 = tid * 2, li1 = tid * 2 + 1;
    const int ar0 = li0 >> 2, ag0 = li0 & 3, ar1 = li1 >> 2, ag1 = li1 & 3;
    int bn0 = n0 + ar0; if (bn0 > NT - 1) bn0 = NT - 1;
    int bn1 = n0 + ar1; if (bn1 > NT - 1) bn1 = NT - 1;

    uint4 pa0, pa1, pb0, pb1;
    pa0 = *reinterpret_cast<const uint4*>(Abm + (size_t)(m0 + ar0) * DIN + ag0 * 8);
    pa1 = *reinterpret_cast<const uint4*>(Abm + (size_t)(m0 + ar1) * DIN + ag1 * 8);
    pb0 = *reinterpret_cast<const uint4*>(Bbm + (size_t)bn0 * DIN + ag0 * 8);
    pb1 = *reinterpret_cast<const uint4*>(Bbm + (size_t)bn1 * DIN + ag1 * 8);

    for (int kt = 0; kt < 16; kt++) {
        __syncthreads();
        *reinterpret_cast<uint4*>(Asp + ar0 * SP + ag0 * 8) = pa0;
        *reinterpret_cast<uint4*>(Asp + ar1 * SP + ag1 * 8) = pa1;
        *reinterpret_cast<uint4*>(Bsp + ar0 * SP + ag0 * 8) = pb0;
        *reinterpret_cast<uint4*>(Bsp + ar1 * SP + ag1 * 8) = pb1;
        __syncthreads();
        if (kt < 15) {
            int k0 = (kt + 1) * 32;
            pa0 = *reinterpret_cast<const uint4*>(Abm + (size_t)(m0 + ar0) * DIN + k0 + ag0 * 8);
            pa1 = *reinterpret_cast<const uint4*>(Abm + (size_t)(m0 + ar1) * DIN + k0 + ag1 * 8);
            pb0 = *reinterpret_cast<const uint4*>(Bbm + (size_t)bn0 * DIN + k0 + ag0 * 8);
            pb1 = *reinterpret_cast<const uint4*>(Bbm + (size_t)bn1 * DIN + k0 + ag1 * 8);
        }
#pragma unroll
        for (int ks = 0; ks < 32; ks += 16) {
            uint32_t af[4][4], bf[4][2];
#pragma unroll
            for (int mt = 0; mt < 4; mt++) {
                int r = wm + mt * 16 + gid;
                int k = ks + tig * 2;
                af[mt][0] = *reinterpret_cast<const uint32_t*>(Asp + r * SP + k);
                af[mt][1] = *reinterpret_cast<const uint32_t*>(Asp + (r + 8) * SP + k);
                af[mt][2] = *reinterpret_cast<const uint32_t*>(Asp + r * SP + k + 8);
                af[mt][3] = *reinterpret_cast<const uint32_t*>(Asp + (r + 8) * SP + k + 8);
            }
#pragma unroll
            for (int nt = 0; nt < 4; nt++) {
                int n = wn + nt * 8 + gid;
                int k = ks + tig * 2;
                bf[nt][0] = *reinterpret_cast<const uint32_t*>(Bsp + n * SP + k);
                bf[nt][1] = *reinterpret_cast<const uint32_t*>(Bsp + n * SP + k + 8);
            }
#pragma unroll
            for (int mt = 0; mt < 4; mt++)
#pragma unroll
                for (int nt = 0; nt < 4; nt++)
                    mma16816(acc[mt][nt], af[mt][0], af[mt][1], af[mt][2], af[mt][3],
                             bf[nt][0], bf[nt][1]);
        }
    }

    __syncthreads();
    float* stg = reinterpret_cast<float*>(smem);
#pragma unroll
    for (int mt = 0; mt < 4; mt++) {
#pragma unroll
        for (int nt = 0; nt < 4; nt++) {
            int r = wm + mt * 16 + gid;
            int c = wn + nt * 8 + tig * 2;
            int n = n0 + c;
            int ncl = (n > NT - 1) ? NT - 1 : n;
            int ncl1 = (n + 1 > NT - 1) ? NT - 1 : n + 1;
            float bv0 = bias[ncl], bv1 = bias[ncl1];
            stg[r * 132 + c]           = acc[mt][nt][0] + bv0;
            stg[r * 132 + c + 1]       = acc[mt][nt][1] + bv1;
            stg[(r + 8) * 132 + c]     = acc[mt][nt][2] + bv0;
            stg[(r + 8) * 132 + c + 1] = acc[mt][nt][3] + bv1;
        }
    }
    __syncthreads();
    int nmax = NT - n0;
    if (nmax > 128) nmax = 128;
    for (int row = wid; row < 128; row += 8) {
        int m = m0 + row;
        int r_out;
        if (REMAP) { int t = m >> 6, b = m & 63; r_out = b * TT + t; }
        else       r_out = m;
        float v0 = -INFINITY, v1 = -INFINITY, v2 = -INFINITY, v3 = -INFINITY;
        int c0 = lid, c1 = lid + 32, c2 = lid + 64, c3 = lid + 96;
        if (OBF) {
            __nv_bfloat16* op = reinterpret_cast<__nv_bfloat16*>(Cp) + (size_t)r_out * ldc + n0;
            if (c0 < nmax) { v0 = stg[row * 132 + c0]; op[c0] = __float2bfloat16(v0); }
            if (c1 < nmax) { v1 = stg[row * 132 + c1]; op[c1] = __float2bfloat16(v1); }
            if (c2 < nmax) { v2 = stg[row * 132 + c2]; op[c2] = __float2bfloat16(v2); }
            if (c3 < nmax) { v3 = stg[row * 132 + c3]; op[c3] = __float2bfloat16(v3); }
        } else {
            float* op = reinterpret_cast<float*>(Cp) + (size_t)r_out * ldc + n0;
            if (c0 < nmax) { v0 = stg[row * 132 + c0]; op[c0] = v0; }
            if (c1 < nmax) { v1 = stg[row * 132 + c1]; op[c1] = v1; }
            if (c2 < nmax) { v2 = stg[row * 132 + c2]; op[c2] = v2; }
            if (c3 < nmax) { v3 = stg[row * 132 + c3]; op[c3] = v3; }
        }
        if (PLSE) {
            float mx = fmaxf(fmaxf(v0, v1), fmaxf(v2, v3));
#pragma unroll
            for (int o = 16; o > 0; o >>= 1)
                mx = fmaxf(mx, __shfl_xor_sync(0xffffffffu, mx, o));
            float s = 0.f;
            if (c0 < nmax) s += __expf(v0 - mx);
            if (c1 < nmax) s += __expf(v1 - mx);
            if (c2 < nmax) s += __expf(v2 - mx);
            if (c3 < nmax) s += __expf(v3 - mx);
#pragma unroll
            for (int o = 16; o > 0; o >>= 1)
                s += __shfl_xor_sync(0xffffffffu, s, o);
            if (lid == 0) {
                g_pmax[(size_t)r_out * NBLK_LG + blockIdx.x] = mx;
                g_psum[(size_t)r_out * NBLK_LG + blockIdx.x] = s;
            }
        }
    }
}

// ================= lse reduce + final output =================
__global__ void lse_reduce() {
    int row = blockIdx.x * 8 + (threadIdx.x >> 5);
    int lid = threadIdx.x & 31;
    float m = -INFINITY, s = 0.f;
    for (int i = lid; i < NBLK_LG; i += 32) {
        float m2 = g_pmax[(size_t)row * NBLK_LG + i];
        float s2 = g_psum[(size_t)row * NBLK_LG + i];
        if (m2 > m) { s = s * __expf(m - m2) + s2; m = m2; }
        else        { s += s2 * __expf(m2 - m); }
    }
#pragma unroll
    for (int o = 16; o > 0; o >>= 1) {
        float m2 = __shfl_xor_sync(0xffffffffu, m, o);
        float s2 = __shfl_xor_sync(0xffffffffu, s, o);
        if (m2 > m) { s = s * __expf(m - m2) + s2; m = m2; }
        else        { s += s2 * __expf(m2 - m); }
    }
    if (lid == 0) g_lse[row] = m + logf(s);
}

__global__ void final_out(float* __restrict__ out) {
    int row = blockIdx.y;
    int v = (blockIdx.x * 256 + threadIdx.x) * 4;
    float l = g_lse[row];
    const __nv_bfloat16* lp = g_lgb + (size_t)row * VP;   // padded: uint2-aligned
    float* op = out + (size_t)row * VOCAB1;               // odd stride: scalar stores
    if (v + 3 < VOCAB1) {
        uint2 u = *reinterpret_cast<const uint2*>(lp + v);
        __nv_bfloat162 p0 = *reinterpret_cast<__nv_bfloat162*>(&u.x);
        __nv_bfloat162 p1 = *reinterpret_cast<__nv_bfloat162*>(&u.y);
        op[v + 0] = __bfloat162float(p0.x) - l;
        op[v + 1] = __bfloat162float(p0.y) - l;
        op[v + 2] = __bfloat162float(p1.x) - l;
        op[v + 3] = __bfloat162float(p1.y) - l;
    } else {
        for (int j = v; j < VOCAB1; j++) op[j] = __bfloat162float(lp[j]) - l;
    }
}

// ================= launch =================
extern "C" void kernel_launch(void* const* d_in, const int* in_sizes, int n_in,
                              void* d_out, int out_size) {
    const float* img_feat = (const float*)d_in[0];
    const int*   seq      = (const int*)d_in[1];
    const float* W_img    = (const float*)d_in[2];
    const float* b_img    = (const float*)d_in[3];
    const float* embed    = (const float*)d_in[4];
    const float* W_ih     = (const float*)d_in[5];
    const float* b_ih     = (const float*)d_in[6];
    const float* W_hh     = (const float*)d_in[7];
    const float* b_hh     = (const float*)d_in[8];
    const float* W_logit  = (const float*)d_in[9];
    const float* b_logit  = (const float*)d_in[10];
    float* out = (float*)d_out;

    float *gx, *bias2;
    __nv_bfloat16 *xsb, *hsb, *wlb, *wib, *whb, *lgb;
    cudaGetSymbolAddress((void**)&gx,    g_gx);
    cudaGetSymbolAddress((void**)&bias2, g_bias2);
    cudaGetSymbolAddress((void**)&xsb,   g_xsb);
    cudaGetSymbolAddress((void**)&hsb,   g_hsb);
    cudaGetSymbolAddress((void**)&wlb,   g_wlb);
    cudaGetSymbolAddress((void**)&wib,   g_wib);
    cudaGetSymbolAddress((void**)&whb,   g_whb);
    cudaGetSymbolAddress((void**)&lgb,   g_lgb);

    cudaFuncSetAttribute(bmma<false, false, false>, cudaFuncAttributeMaxDynamicSharedMemorySize, LG_DSMEM);
    cudaFuncSetAttribute(bmma<true, true, true>,    cudaFuncAttributeMaxDynamicSharedMemorySize, LG_DSMEM);
    cudaFuncSetAttribute(lstm_step, cudaFuncAttributeMaxDynamicSharedMemorySize, ST_SMEM);

    init_k<<<128, 256>>>(b_ih, b_hh);
    gather_embed<<<dim3(19, 64), 128>>>(seq, embed);
    conv_bf16<<<((size_t)VOCAB1 * DR / 4 + 255) / 256, 256>>>(W_logit, wlb, (size_t)VOCAB1 * DR);
    conv_bf16<<<((size_t)G4 * DIN / 4 + 255) / 256, 256>>>(W_ih, wib, (size_t)G4 * DIN);
    conv_bf16<<<((size_t)G4 * DR / 4 + 255) / 256, 256>>>(W_hh, whb, (size_t)G4 * DR);

    x0_ksplit<<<dim3(8, 8), 256>>>(img_feat, W_img);
    x0_reduce<<<(BB * DIN) / 256, 256>>>(b_img);

    bmma<false, false, false><<<dim3(16, 10), 256, LG_DSMEM>>>(xsb, wib, bias2, gx, G4, G4);

    for (int t = 0; t < TT; t++)
        lstm_step<<<64, 256, ST_SMEM>>>(t);

    bmma<true, true, true><<<dim3(NBLK_LG, 10), 256, LG_DSMEM>>>(hsb, wlb, b_logit, lgb, VOCAB1, VP);

    lse_reduce<<<BB * TT / 8, 256>>>();
    final_out<<<dim3(32, BB * TT), 256>>>(out);
}

// round 10
// speedup vs baseline: 3.4586x; 1.1357x over previous
#include <cuda_runtime.h>
#include <cuda_bf16.h>
#include <math.h>
#include <stdint.h>

#define VOCAB1 32001
#define VP     32004
#define DIN 512
#define DR  512
#define DF  2048
#define BB  64
#define TT  20
#define G4  2048
#define NBLK_LG 251

// ================= device scratch =================
__device__ __align__(16) __nv_bfloat16 g_xsb[TT * BB * DIN];
__device__ __align__(16) float g_gx[(size_t)TT * BB * G4];
__device__ __align__(16) float g_c[BB * DR];
__device__ __align__(16) __nv_bfloat16 g_hb[BB * DR];
__device__ __align__(16) __nv_bfloat16 g_hsb[TT * BB * DR];
__device__ __align__(16) __nv_bfloat16 g_wlb[(size_t)VOCAB1 * DR];
__device__ __align__(16) __nv_bfloat16 g_wib[(size_t)G4 * DIN];
__device__ __align__(16) __nv_bfloat16 g_whb[(size_t)G4 * DR];
__device__ __align__(16) float g_bias2[G4];
__device__ __align__(16) float g_lse[BB * TT];
__device__ __align__(16) float g_x0p[8 * BB * DIN];
__device__ __align__(16) float g_pmax[BB * TT * NBLK_LG];
__device__ __align__(16) float g_psum[BB * TT * NBLK_LG];
__device__ __align__(16) __nv_bfloat16 g_lgb[(size_t)BB * TT * VP];
__device__ int g_cnt;

// ================= small kernels =================
__global__ void init_k(const float* __restrict__ b_ih, const float* __restrict__ b_hh) {
    int id = blockIdx.x * blockDim.x + threadIdx.x;
    if (id < BB * DR) g_c[id] = 0.f;
    if (id < G4) g_bias2[id] = b_ih[id] + b_hh[id];
    if (id == 0) g_cnt = 0;
}

__global__ void gather_embed(const int* __restrict__ seq, const float* __restrict__ embed) {
    int t = 1 + blockIdx.x, b = blockIdx.y;
    int idx = seq[b * TT + t];
    if (idx < 0) idx = 0;
    if (idx > VOCAB1 - 1) idx = VOCAB1 - 1;
    float4 v = reinterpret_cast<const float4*>(embed + (size_t)idx * DIN)[threadIdx.x];
    __nv_bfloat162 p0 = __floats2bfloat162_rn(v.x, v.y);
    __nv_bfloat162 p1 = __floats2bfloat162_rn(v.z, v.w);
    uint2 u;
    u.x = *reinterpret_cast<uint32_t*>(&p0);
    u.y = *reinterpret_cast<uint32_t*>(&p1);
    reinterpret_cast<uint2*>(g_xsb + ((size_t)t * BB + b) * DIN)[threadIdx.x] = u;
}

__global__ void conv_bf16(const float* __restrict__ w, __nv_bfloat16* __restrict__ dst, size_t n) {
    size_t i = ((size_t)blockIdx.x * blockDim.x + threadIdx.x) * 4;
    if (i + 3 < n) {
        float4 v = *reinterpret_cast<const float4*>(w + i);
        __nv_bfloat162 p0 = __floats2bfloat162_rn(v.x, v.y);
        __nv_bfloat162 p1 = __floats2bfloat162_rn(v.z, v.w);
        uint2 u;
        u.x = *reinterpret_cast<uint32_t*>(&p0);
        u.y = *reinterpret_cast<uint32_t*>(&p1);
        *reinterpret_cast<uint2*>(&dst[i]) = u;
    }
}

// ================= x0: k-split fp32 GEMM =================
__global__ void x0_ksplit(const float* __restrict__ A, const float* __restrict__ Bm) {
    __shared__ float As[16][64];
    __shared__ float Bs[16][64];
    const int tid = threadIdx.x;
    const int n0 = blockIdx.x * 64;
    const int kbeg = blockIdx.y * 256;
    const int tx = tid & 15, ty = tid >> 4;
    float acc[4][4] = {};
    for (int kt = 0; kt < 256; kt += 16) {
        {
            int row = tid >> 2, kq = (tid & 3) << 2;
            float4 v = *reinterpret_cast<const float4*>(A + (size_t)row * DF + kbeg + kt + kq);
            As[kq + 0][row] = v.x; As[kq + 1][row] = v.y;
            As[kq + 2][row] = v.z; As[kq + 3][row] = v.w;
        }
        {
            int row = tid >> 2, kq = (tid & 3) << 2;
            float4 v = *reinterpret_cast<const float4*>(Bm + (size_t)(n0 + row) * DF + kbeg + kt + kq);
            Bs[kq + 0][row] = v.x; Bs[kq + 1][row] = v.y;
            Bs[kq + 2][row] = v.z; Bs[kq + 3][row] = v.w;
        }
        __syncthreads();
#pragma unroll
        for (int k = 0; k < 16; k++) {
            float a[4], b[4];
#pragma unroll
            for (int i = 0; i < 4; i++) a[i] = As[k][ty * 4 + i];
#pragma unroll
            for (int j = 0; j < 4; j++) b[j] = Bs[k][tx * 4 + j];
#pragma unroll
            for (int i = 0; i < 4; i++)
#pragma unroll
                for (int j = 0; j < 4; j++) acc[i][j] = fmaf(a[i], b[j], acc[i][j]);
        }
        __syncthreads();
    }
    float* p = g_x0p + (size_t)blockIdx.y * BB * DIN;
#pragma unroll
    for (int i = 0; i < 4; i++)
#pragma unroll
        for (int j = 0; j < 4; j++)
            p[(ty * 4 + i) * DIN + n0 + tx * 4 + j] = acc[i][j];
}

__global__ void x0_reduce(const float* __restrict__ b_img) {
    int id = blockIdx.x * blockDim.x + threadIdx.x;
    float s = b_img[id & 511];
#pragma unroll
    for (int kb = 0; kb < 8; kb++) s += g_x0p[kb * BB * DIN + id];
    g_xsb[id] = __float2bfloat16(s);
}

// ================= mma primitive =================
__device__ __forceinline__ void mma16816(float* d, uint32_t a0, uint32_t a1,
                                         uint32_t a2, uint32_t a3,
                                         uint32_t b0, uint32_t b1) {
    asm volatile(
        "mma.sync.aligned.m16n8k16.row.col.f32.bf16.bf16.f32 "
        "{%0,%1,%2,%3}, {%4,%5,%6,%7}, {%8,%9}, {%0,%1,%2,%3};"
        : "+f"(d[0]), "+f"(d[1]), "+f"(d[2]), "+f"(d[3])
        : "r"(a0), "r"(a1), "r"(a2), "r"(a3), "r"(b0), "r"(b1));
}

__device__ __forceinline__ float sigmoidf_(float x) { return 1.f / (1.f + __expf(-x)); }

__device__ __forceinline__ uint4 ldcg_v4(const uint4* p) {
    uint4 v;
    asm volatile("ld.global.cg.v4.u32 {%0,%1,%2,%3}, [%4];"
                 : "=r"(v.x), "=r"(v.y), "=r"(v.z), "=r"(v.w) : "l"(p));
    return v;
}

// ================= persistent LSTM: 64 CTAs, single launch =================
// CTA owns gate cols {q*512 + cta*8 + j}. Cross-CTA h exchange via g_hb (L2, .cg)
// guarded by a release-fenced global counter. 64 CTAs @ 108KB smem -> all resident.
#define HSTR 520
#define ST_SMEM (64 * HSTR * 2 + 32 * HSTR * 2 + 64 * 33 * 4)

__global__ void __launch_bounds__(256) lstm_persist64() {
    extern __shared__ char smem[];
    __nv_bfloat16* hS = reinterpret_cast<__nv_bfloat16*>(smem);
    __nv_bfloat16* wS = reinterpret_cast<__nv_bfloat16*>(smem + 64 * HSTR * 2);
    float* gS = reinterpret_cast<float*>(smem + 64 * HSTR * 2 + 32 * HSTR * 2);
    const int tid = threadIdx.x, wid = tid >> 5, lid = tid & 31;
    const int gid = lid >> 2, tig = lid & 3;
    const int cta = blockIdx.x;
    const int c0 = cta * 8;

    // stage W slice ONCE: row j -> Whh row (j>>3)*512 + c0 + (j&7)
    for (int q = tid; q < 2048; q += 256) {
        int j = q >> 6, g = q & 63;
        int wr = (j >> 3) * 512 + c0 + (j & 7);
        *reinterpret_cast<uint4*>(wS + j * HSTR + g * 8) =
            reinterpret_cast<const uint4*>(g_whb + (size_t)wr * DR)[g];
    }
    __syncthreads();

    const int mrow = (wid >> 1) * 16;
    const int ncol = (wid & 1) * 16;

    for (int t = 0; t < TT; t++) {
        if (t > 0) {
            // wait for all 64 CTAs to have published h(t-1)
            if (tid == 0) {
                int target = 64 * t, v;
                long guard = 0;
                do {
                    asm volatile("ld.global.cg.s32 %0, [%1];" : "=r"(v) : "l"(&g_cnt));
                } while (v < target && ++guard < (1L << 31));
            }
            __syncthreads();
            // stage h(t-1) from L2 (.cg: L1 is stale for reused addresses)
            {
                const uint4* src = reinterpret_cast<const uint4*>(g_hb);
                for (int q = tid; q < 4096; q += 256) {
                    int row = q >> 6, g = q & 63;
                    *reinterpret_cast<uint4*>(hS + row * HSTR + g * 8) = ldcg_v4(src + row * 64 + g);
                }
            }
            __syncthreads();
            float acc[2][4] = {};
#pragma unroll 4
            for (int ks = 0; ks < 512; ks += 16) {
                const __nv_bfloat16* ap = hS + (mrow + gid) * HSTR + ks + tig * 2;
                uint32_t a0 = *reinterpret_cast<const uint32_t*>(ap);
                uint32_t a1 = *reinterpret_cast<const uint32_t*>(ap + 8 * HSTR);
                uint32_t a2 = *reinterpret_cast<const uint32_t*>(ap + 8);
                uint32_t a3 = *reinterpret_cast<const uint32_t*>(ap + 8 * HSTR + 8);
#pragma unroll
                for (int nt = 0; nt < 2; nt++) {
                    const __nv_bfloat16* bp = wS + (ncol + nt * 8 + gid) * HSTR + ks + tig * 2;
                    uint32_t b0 = *reinterpret_cast<const uint32_t*>(bp);
                    uint32_t b1 = *reinterpret_cast<const uint32_t*>(bp + 8);
                    mma16816(acc[nt], a0, a1, a2, a3, b0, b1);
                }
            }
#pragma unroll
            for (int nt = 0; nt < 2; nt++) {
                int r0 = mrow + gid;
                int c = ncol + nt * 8 + tig * 2;
                gS[r0 * 33 + c]           = acc[nt][0];
                gS[r0 * 33 + c + 1]       = acc[nt][1];
                gS[(r0 + 8) * 33 + c]     = acc[nt][2];
                gS[(r0 + 8) * 33 + c + 1] = acc[nt][3];
            }
            __syncthreads();
        }

        // elementwise for this CTA's 64x8 slice
#pragma unroll
        for (int e = tid; e < 512; e += 256) {
            int b = e >> 3, jl = e & 7;
            int r = c0 + jl;
            const float* gxp = g_gx + ((size_t)t * BB + b) * G4;
            float gi = gxp[r], gf = gxp[512 + r], gg = gxp[1024 + r], go = gxp[1536 + r];
            if (t > 0) {
                gi += gS[b * 33 + jl];
                gf += gS[b * 33 + 8 + jl];
                gg += gS[b * 33 + 16 + jl];
                go += gS[b * 33 + 24 + jl];
            }
            int id = b * DR + r;
            float c = (t > 0) ? g_c[id] : 0.f;   // CTA-private (same SM/L1)
            float cn = sigmoidf_(gf) * c + sigmoidf_(gi) * tanhf(gg);
            float hn = sigmoidf_(go) * tanhf(cn);
            g_c[id] = cn;
            __nv_bfloat16 hb = __float2bfloat16(hn);
            g_hb[id] = hb;
            g_hsb[(size_t)t * BB * DR + id] = hb;
        }
        __syncthreads();                         // all h stores issued
        if (tid == 0) {
            __threadfence();                     // cumulative: flush CTA's stores to L2
            atomicAdd(&g_cnt, 1);                // publish step completion
        }
    }
}

// ================= generic bf16 mma GEMM (m16n8k16), K=512 =================
#define SP 40
#define LG_DSMEM (128 * 132 * 4)

template <bool REMAP, bool PLSE, bool OBF>
__global__ void __launch_bounds__(256) bmma(const __nv_bfloat16* __restrict__ Abm,
                                            const __nv_bfloat16* __restrict__ Bbm,
                                            const float* __restrict__ bias,
                                            void* __restrict__ Cp, int NT, int ldc) {
    extern __shared__ char smem[];
    __nv_bfloat16* Asp = reinterpret_cast<__nv_bfloat16*>(smem);
    __nv_bfloat16* Bsp = reinterpret_cast<__nv_bfloat16*>(smem + 10240);
    const int tid = threadIdx.x, wid = tid >> 5, lid = tid & 31;
    const int gid = lid >> 2, tig = lid & 3;
    const int n0 = blockIdx.x * 128;
    const int m0 = blockIdx.y * 128;
    const int wm = (wid >> 2) * 64;
    const int wn = (wid & 3) * 32;

    float acc[4][4][4];
#pragma unroll
    for (int i = 0; i < 4; i++)
#pragma unroll
        for (int j = 0; j < 4; j++)
#pragma unroll
            for (int r = 0; r < 4; r++) acc[i][j][r] = 0.f;

    const int li0 = tid * 2, li1 = tid * 2 + 1;
    const int ar0 = li0 >> 2, ag0 = li0 & 3, ar1 = li1 >> 2, ag1 = li1 & 3;
    int bn0 = n0 + ar0; if (bn0 > NT - 1) bn0 = NT - 1;
    int bn1 = n0 + ar1; if (bn1 > NT - 1) bn1 = NT - 1;

    uint4 pa0, pa1, pb0, pb1;
    pa0 = *reinterpret_cast<const uint4*>(Abm + (size_t)(m0 + ar0) * DIN + ag0 * 8);
    pa1 = *reinterpret_cast<const uint4*>(Abm + (size_t)(m0 + ar1) * DIN + ag1 * 8);
    pb0 = *reinterpret_cast<const uint4*>(Bbm + (size_t)bn0 * DIN + ag0 * 8);
    pb1 = *reinterpret_cast<const uint4*>(Bbm + (size_t)bn1 * DIN + ag1 * 8);

    for (int kt = 0; kt < 16; kt++) {
        __syncthreads();
        *reinterpret_cast<uint4*>(Asp + ar0 * SP + ag0 * 8) = pa0;
        *reinterpret_cast<uint4*>(Asp + ar1 * SP + ag1 * 8) = pa1;
        *reinterpret_cast<uint4*>(Bsp + ar0 * SP + ag0 * 8) = pb0;
        *reinterpret_cast<uint4*>(Bsp + ar1 * SP + ag1 * 8) = pb1;
        __syncthreads();
        if (kt < 15) {
            int k0 = (kt + 1) * 32;
            pa0 = *reinterpret_cast<const uint4*>(Abm + (size_t)(m0 + ar0) * DIN + k0 + ag0 * 8);
            pa1 = *reinterpret_cast<const uint4*>(Abm + (size_t)(m0 + ar1) * DIN + k0 + ag1 * 8);
            pb0 = *reinterpret_cast<const uint4*>(Bbm + (size_t)bn0 * DIN + k0 + ag0 * 8);
            pb1 = *reinterpret_cast<const uint4*>(Bbm + (size_t)bn1 * DIN + k0 + ag1 * 8);
        }
#pragma unroll
        for (int ks = 0; ks < 32; ks += 16) {
            uint32_t af[4][4], bf[4][2];
#pragma unroll
            for (int mt = 0; mt < 4; mt++) {
                int r = wm + mt * 16 + gid;
                int k = ks + tig * 2;
                af[mt][0] = *reinterpret_cast<const uint32_t*>(Asp + r * SP + k);
                af[mt][1] = *reinterpret_cast<const uint32_t*>(Asp + (r + 8) * SP + k);
                af[mt][2] = *reinterpret_cast<const uint32_t*>(Asp + r * SP + k + 8);
                af[mt][3] = *reinterpret_cast<const uint32_t*>(Asp + (r + 8) * SP + k + 8);
            }
#pragma unroll
            for (int nt = 0; nt < 4; nt++) {
                int n = wn + nt * 8 + gid;
                int k = ks + tig * 2;
                bf[nt][0] = *reinterpret_cast<const uint32_t*>(Bsp + n * SP + k);
                bf[nt][1] = *reinterpret_cast<const uint32_t*>(Bsp + n * SP + k + 8);
            }
#pragma unroll
            for (int mt = 0; mt < 4; mt++)
#pragma unroll
                for (int nt = 0; nt < 4; nt++)
                    mma16816(acc[mt][nt], af[mt][0], af[mt][1], af[mt][2], af[mt][3],
                             bf[nt][0], bf[nt][1]);
        }
    }

    __syncthreads();
    float* stg = reinterpret_cast<float*>(smem);
#pragma unroll
    for (int mt = 0; mt < 4; mt++) {
#pragma unroll
        for (int nt = 0; nt < 4; nt++) {
            int r = wm + mt * 16 + gid;
            int c = wn + nt * 8 + tig * 2;
            int n = n0 + c;
            int ncl = (n > NT - 1) ? NT - 1 : n;
            int ncl1 = (n + 1 > NT - 1) ? NT - 1 : n + 1;
            float bv0 = bias[ncl], bv1 = bias[ncl1];
            stg[r * 132 + c]           = acc[mt][nt][0] + bv0;
            stg[r * 132 + c + 1]       = acc[mt][nt][1] + bv1;
            stg[(r + 8) * 132 + c]     = acc[mt][nt][2] + bv0;
            stg[(r + 8) * 132 + c + 1] = acc[mt][nt][3] + bv1;
        }
    }
    __syncthreads();
    int nmax = NT - n0;
    if (nmax > 128) nmax = 128;
    for (int row = wid; row < 128; row += 8) {
        int m = m0 + row;
        int r_out;
        if (REMAP) { int t = m >> 6, b = m & 63; r_out = b * TT + t; }
        else       r_out = m;
        float v0 = -INFINITY, v1 = -INFINITY, v2 = -INFINITY, v3 = -INFINITY;
        int c0 = lid, c1 = lid + 32, c2 = lid + 64, c3 = lid + 96;
        if (OBF) {
            __nv_bfloat16* op = reinterpret_cast<__nv_bfloat16*>(Cp) + (size_t)r_out * ldc + n0;
            if (c0 < nmax) { v0 = stg[row * 132 + c0]; op[c0] = __float2bfloat16(v0); }
            if (c1 < nmax) { v1 = stg[row * 132 + c1]; op[c1] = __float2bfloat16(v1); }
            if (c2 < nmax) { v2 = stg[row * 132 + c2]; op[c2] = __float2bfloat16(v2); }
            if (c3 < nmax) { v3 = stg[row * 132 + c3]; op[c3] = __float2bfloat16(v3); }
        } else {
            float* op = reinterpret_cast<float*>(Cp) + (size_t)r_out * ldc + n0;
            if (c0 < nmax) { v0 = stg[row * 132 + c0]; op[c0] = v0; }
            if (c1 < nmax) { v1 = stg[row * 132 + c1]; op[c1] = v1; }
            if (c2 < nmax) { v2 = stg[row * 132 + c2]; op[c2] = v2; }
            if (c3 < nmax) { v3 = stg[row * 132 + c3]; op[c3] = v3; }
        }
        if (PLSE) {
            float mx = fmaxf(fmaxf(v0, v1), fmaxf(v2, v3));
#pragma unroll
            for (int o = 16; o > 0; o >>= 1)
                mx = fmaxf(mx, __shfl_xor_sync(0xffffffffu, mx, o));
            float s = 0.f;
            if (c0 < nmax) s += __expf(v0 - mx);
            if (c1 < nmax) s += __expf(v1 - mx);
            if (c2 < nmax) s += __expf(v2 - mx);
            if (c3 < nmax) s += __expf(v3 - mx);
#pragma unroll
            for (int o = 16; o > 0; o >>= 1)
                s += __shfl_xor_sync(0xffffffffu, s, o);
            if (lid == 0) {
                g_pmax[(size_t)r_out * NBLK_LG + blockIdx.x] = mx;
                g_psum[(size_t)r_out * NBLK_LG + blockIdx.x] = s;
            }
        }
    }
}

// ================= lse reduce + final output =================
__global__ void lse_reduce() {
    int row = blockIdx.x * 8 + (threadIdx.x >> 5);
    int lid = threadIdx.x & 31;
    float m = -INFINITY, s = 0.f;
    for (int i = lid; i < NBLK_LG; i += 32) {
        float m2 = g_pmax[(size_t)row * NBLK_LG + i];
        float s2 = g_psum[(size_t)row * NBLK_LG + i];
        if (m2 > m) { s = s * __expf(m - m2) + s2; m = m2; }
        else        { s += s2 * __expf(m2 - m); }
    }
#pragma unroll
    for (int o = 16; o > 0; o >>= 1) {
        float m2 = __shfl_xor_sync(0xffffffffu, m, o);
        float s2 = __shfl_xor_sync(0xffffffffu, s, o);
        if (m2 > m) { s = s * __expf(m - m2) + s2; m = m2; }
        else        { s += s2 * __expf(m2 - m); }
    }
    if (lid == 0) g_lse[row] = m + logf(s);
}

__global__ void final_out(float* __restrict__ out) {
    int row = blockIdx.y;
    int v = (blockIdx.x * 256 + threadIdx.x) * 4;
    float l = g_lse[row];
    const __nv_bfloat16* lp = g_lgb + (size_t)row * VP;
    float* op = out + (size_t)row * VOCAB1;
    if (v + 3 < VOCAB1) {
        uint2 u = *reinterpret_cast<const uint2*>(lp + v);
        __nv_bfloat162 p0 = *reinterpret_cast<__nv_bfloat162*>(&u.x);
        __nv_bfloat162 p1 = *reinterpret_cast<__nv_bfloat162*>(&u.y);
        op[v + 0] = __bfloat162float(p0.x) - l;
        op[v + 1] = __bfloat162float(p0.y) - l;
        op[v + 2] = __bfloat162float(p1.x) - l;
        op[v + 3] = __bfloat162float(p1.y) - l;
    } else {
        for (int j = v; j < VOCAB1; j++) op[j] = __bfloat162float(lp[j]) - l;
    }
}

// ================= launch =================
extern "C" void kernel_launch(void* const* d_in, const int* in_sizes, int n_in,
                              void* d_out, int out_size) {
    const float* img_feat = (const float*)d_in[0];
    const int*   seq      = (const int*)d_in[1];
    const float* W_img    = (const float*)d_in[2];
    const float* b_img    = (const float*)d_in[3];
    const float* embed    = (const float*)d_in[4];
    const float* W_ih     = (const float*)d_in[5];
    const float* b_ih     = (const float*)d_in[6];
    const float* W_hh     = (const float*)d_in[7];
    const float* b_hh     = (const float*)d_in[8];
    const float* W_logit  = (const float*)d_in[9];
    const float* b_logit  = (const float*)d_in[10];
    float* out = (float*)d_out;

    float *gx, *bias2;
    __nv_bfloat16 *xsb, *hsb, *wlb, *wib, *whb, *lgb;
    cudaGetSymbolAddress((void**)&gx,    g_gx);
    cudaGetSymbolAddress((void**)&bias2, g_bias2);
    cudaGetSymbolAddress((void**)&xsb,   g_xsb);
    cudaGetSymbolAddress((void**)&hsb,   g_hsb);
    cudaGetSymbolAddress((void**)&wlb,   g_wlb);
    cudaGetSymbolAddress((void**)&wib,   g_wib);
    cudaGetSymbolAddress((void**)&whb,   g_whb);
    cudaGetSymbolAddress((void**)&lgb,   g_lgb);

    cudaFuncSetAttribute(bmma<false, false, false>, cudaFuncAttributeMaxDynamicSharedMemorySize, LG_DSMEM);
    cudaFuncSetAttribute(bmma<true, true, true>,    cudaFuncAttributeMaxDynamicSharedMemorySize, LG_DSMEM);
    cudaFuncSetAttribute(lstm_persist64, cudaFuncAttributeMaxDynamicSharedMemorySize, ST_SMEM);

    init_k<<<128, 256>>>(b_ih, b_hh);
    gather_embed<<<dim3(19, 64), 128>>>(seq, embed);
    conv_bf16<<<((size_t)VOCAB1 * DR / 4 + 255) / 256, 256>>>(W_logit, wlb, (size_t)VOCAB1 * DR);
    conv_bf16<<<((size_t)G4 * DIN / 4 + 255) / 256, 256>>>(W_ih, wib, (size_t)G4 * DIN);
    conv_bf16<<<((size_t)G4 * DR / 4 + 255) / 256, 256>>>(W_hh, whb, (size_t)G4 * DR);

    x0_ksplit<<<dim3(8, 8), 256>>>(img_feat, W_img);
    x0_reduce<<<(BB * DIN) / 256, 256>>>(b_img);

    bmma<false, false, false><<<dim3(16, 10), 256, LG_DSMEM>>>(xsb, wib, bias2, gx, G4, G4);

    lstm_persist64<<<64, 256, ST_SMEM>>>();

    bmma<true, true, true><<<dim3(NBLK_LG, 10), 256, LG_DSMEM>>>(hsb, wlb, b_logit, lgb, VOCAB1, VP);

    lse_reduce<<<BB * TT / 8, 256>>>();
    final_out<<<dim3(32, BB * TT), 256>>>(out);
}

// round 11
// speedup vs baseline: 3.5066x; 1.0139x over previous
#include <cuda_runtime.h>
#include <cuda_bf16.h>
#include <cuda_fp8.h>
#include <math.h>
#include <stdint.h>

#define VOCAB1 32001
#define VP     32004
#define DIN 512
#define DR  512
#define DF  2048
#define BB  64
#define TT  20
#define G4  2048
#define NBLK_LG 251

// ================= device scratch =================
__device__ __align__(16) __nv_bfloat16 g_xsb[TT * BB * DIN];
__device__ __align__(16) float g_gx[(size_t)TT * BB * G4];
__device__ __align__(16) float g_c[BB * DR];
__device__ __align__(16) __nv_bfloat16 g_hb[BB * DR];              // bf16 h (recurrence)
__device__ __align__(16) unsigned char g_hs8[TT * BB * DR];        // fp8 h*64 (logits A)
__device__ __align__(16) unsigned char g_wl8[(size_t)VOCAB1 * DR]; // fp8 W_logit*64
__device__ __align__(16) __nv_bfloat16 g_wib[(size_t)G4 * DIN];
__device__ __align__(16) __nv_bfloat16 g_whb[(size_t)G4 * DR];
__device__ __align__(16) float g_bias2[G4];
__device__ __align__(16) float g_lse[BB * TT];
__device__ __align__(16) float g_x0p[8 * BB * DIN];
__device__ __align__(16) float g_pmax[BB * TT * NBLK_LG];
__device__ __align__(16) float g_psum[BB * TT * NBLK_LG];
__device__ __align__(16) __nv_bfloat16 g_lgb[(size_t)BB * TT * VP];
__device__ int g_cnt;

// ================= small kernels =================
__global__ void init_k(const float* __restrict__ b_ih, const float* __restrict__ b_hh) {
    int id = blockIdx.x * blockDim.x + threadIdx.x;
    if (id < BB * DR) g_c[id] = 0.f;
    if (id < G4) g_bias2[id] = b_ih[id] + b_hh[id];
    if (id == 0) g_cnt = 0;
}

__global__ void gather_embed(const int* __restrict__ seq, const float* __restrict__ embed) {
    int t = 1 + blockIdx.x, b = blockIdx.y;
    int idx = seq[b * TT + t];
    if (idx < 0) idx = 0;
    if (idx > VOCAB1 - 1) idx = VOCAB1 - 1;
    float4 v = reinterpret_cast<const float4*>(embed + (size_t)idx * DIN)[threadIdx.x];
    __nv_bfloat162 p0 = __floats2bfloat162_rn(v.x, v.y);
    __nv_bfloat162 p1 = __floats2bfloat162_rn(v.z, v.w);
    uint2 u;
    u.x = *reinterpret_cast<uint32_t*>(&p0);
    u.y = *reinterpret_cast<uint32_t*>(&p1);
    reinterpret_cast<uint2*>(g_xsb + ((size_t)t * BB + b) * DIN)[threadIdx.x] = u;
}

__global__ void conv_bf16(const float* __restrict__ w, __nv_bfloat16* __restrict__ dst, size_t n) {
    size_t i = ((size_t)blockIdx.x * blockDim.x + threadIdx.x) * 4;
    if (i + 3 < n) {
        float4 v = *reinterpret_cast<const float4*>(w + i);
        __nv_bfloat162 p0 = __floats2bfloat162_rn(v.x, v.y);
        __nv_bfloat162 p1 = __floats2bfloat162_rn(v.z, v.w);
        uint2 u;
        u.x = *reinterpret_cast<uint32_t*>(&p0);
        u.y = *reinterpret_cast<uint32_t*>(&p1);
        *reinterpret_cast<uint2*>(&dst[i]) = u;
    }
}

// W_logit -> e4m3, scaled x64 (keeps typical |w| in the normal range)
__global__ void conv_fp8(const float* __restrict__ w, unsigned char* __restrict__ dst, size_t n) {
    size_t i = ((size_t)blockIdx.x * blockDim.x + threadIdx.x) * 4;
    if (i + 3 < n) {
        float4 v = *reinterpret_cast<const float4*>(w + i);
        uint32_t r =
            (uint32_t)__nv_cvt_float_to_fp8(v.x * 64.f, __NV_SATFINITE, __NV_E4M3)
          | ((uint32_t)__nv_cvt_float_to_fp8(v.y * 64.f, __NV_SATFINITE, __NV_E4M3) << 8)
          | ((uint32_t)__nv_cvt_float_to_fp8(v.z * 64.f, __NV_SATFINITE, __NV_E4M3) << 16)
          | ((uint32_t)__nv_cvt_float_to_fp8(v.w * 64.f, __NV_SATFINITE, __NV_E4M3) << 24);
        *reinterpret_cast<uint32_t*>(dst + i) = r;
    }
}

// ================= x0: k-split fp32 GEMM =================
__global__ void x0_ksplit(const float* __restrict__ A, const float* __restrict__ Bm) {
    __shared__ float As[16][64];
    __shared__ float Bs[16][64];
    const int tid = threadIdx.x;
    const int n0 = blockIdx.x * 64;
    const int kbeg = blockIdx.y * 256;
    const int tx = tid & 15, ty = tid >> 4;
    float acc[4][4] = {};
    for (int kt = 0; kt < 256; kt += 16) {
        {
            int row = tid >> 2, kq = (tid & 3) << 2;
            float4 v = *reinterpret_cast<const float4*>(A + (size_t)row * DF + kbeg + kt + kq);
            As[kq + 0][row] = v.x; As[kq + 1][row] = v.y;
            As[kq + 2][row] = v.z; As[kq + 3][row] = v.w;
        }
        {
            int row = tid >> 2, kq = (tid & 3) << 2;
            float4 v = *reinterpret_cast<const float4*>(Bm + (size_t)(n0 + row) * DF + kbeg + kt + kq);
            Bs[kq + 0][row] = v.x; Bs[kq + 1][row] = v.y;
            Bs[kq + 2][row] = v.z; Bs[kq + 3][row] = v.w;
        }
        __syncthreads();
#pragma unroll
        for (int k = 0; k < 16; k++) {
            float a[4], b[4];
#pragma unroll
            for (int i = 0; i < 4; i++) a[i] = As[k][ty * 4 + i];
#pragma unroll
            for (int j = 0; j < 4; j++) b[j] = Bs[k][tx * 4 + j];
#pragma unroll
            for (int i = 0; i < 4; i++)
#pragma unroll
                for (int j = 0; j < 4; j++) acc[i][j] = fmaf(a[i], b[j], acc[i][j]);
        }
        __syncthreads();
    }
    float* p = g_x0p + (size_t)blockIdx.y * BB * DIN;
#pragma unroll
    for (int i = 0; i < 4; i++)
#pragma unroll
        for (int j = 0; j < 4; j++)
            p[(ty * 4 + i) * DIN + n0 + tx * 4 + j] = acc[i][j];
}

__global__ void x0_reduce(const float* __restrict__ b_img) {
    int id = blockIdx.x * blockDim.x + threadIdx.x;
    float s = b_img[id & 511];
#pragma unroll
    for (int kb = 0; kb < 8; kb++) s += g_x0p[kb * BB * DIN + id];
    g_xsb[id] = __float2bfloat16(s);
}

// ================= mma primitives =================
__device__ __forceinline__ void mma16816(float* d, uint32_t a0, uint32_t a1,
                                         uint32_t a2, uint32_t a3,
                                         uint32_t b0, uint32_t b1) {
    asm volatile(
        "mma.sync.aligned.m16n8k16.row.col.f32.bf16.bf16.f32 "
        "{%0,%1,%2,%3}, {%4,%5,%6,%7}, {%8,%9}, {%0,%1,%2,%3};"
        : "+f"(d[0]), "+f"(d[1]), "+f"(d[2]), "+f"(d[3])
        : "r"(a0), "r"(a1), "r"(a2), "r"(a3), "r"(b0), "r"(b1));
}

__device__ __forceinline__ void mma_fp8(float* d, uint32_t a0, uint32_t a1,
                                        uint32_t a2, uint32_t a3,
                                        uint32_t b0, uint32_t b1) {
    asm volatile(
        "mma.sync.aligned.m16n8k32.row.col.f32.e4m3.e4m3.f32 "
        "{%0,%1,%2,%3}, {%4,%5,%6,%7}, {%8,%9}, {%0,%1,%2,%3};"
        : "+f"(d[0]), "+f"(d[1]), "+f"(d[2]), "+f"(d[3])
        : "r"(a0), "r"(a1), "r"(a2), "r"(a3), "r"(b0), "r"(b1));
}

__device__ __forceinline__ float sigmoidf_(float x) { return 1.f / (1.f + __expf(-x)); }

__device__ __forceinline__ uint4 ldcg_v4(const uint4* p) {
    uint4 v;
    asm volatile("ld.global.cg.v4.u32 {%0,%1,%2,%3}, [%4];"
                 : "=r"(v.x), "=r"(v.y), "=r"(v.z), "=r"(v.w) : "l"(p));
    return v;
}

// ================= persistent LSTM (64 CTAs, single launch) =================
#define HSTR 520
#define ST_SMEM (64 * HSTR * 2 + 32 * HSTR * 2 + 64 * 33 * 4)

__global__ void __launch_bounds__(256) lstm_persist64() {
    extern __shared__ char smem[];
    __nv_bfloat16* hS = reinterpret_cast<__nv_bfloat16*>(smem);
    __nv_bfloat16* wS = reinterpret_cast<__nv_bfloat16*>(smem + 64 * HSTR * 2);
    float* gS = reinterpret_cast<float*>(smem + 64 * HSTR * 2 + 32 * HSTR * 2);
    const int tid = threadIdx.x, wid = tid >> 5, lid = tid & 31;
    const int gid = lid >> 2, tig = lid & 3;
    const int cta = blockIdx.x;
    const int c0 = cta * 8;

    for (int q = tid; q < 2048; q += 256) {
        int j = q >> 6, g = q & 63;
        int wr = (j >> 3) * 512 + c0 + (j & 7);
        *reinterpret_cast<uint4*>(wS + j * HSTR + g * 8) =
            reinterpret_cast<const uint4*>(g_whb + (size_t)wr * DR)[g];
    }
    __syncthreads();

    const int mrow = (wid >> 1) * 16;
    const int ncol = (wid & 1) * 16;

    for (int t = 0; t < TT; t++) {
        if (t > 0) {
            if (tid == 0) {
                int target = 64 * t, v;
                long guard = 0;
                do {
                    asm volatile("ld.global.cg.s32 %0, [%1];" : "=r"(v) : "l"(&g_cnt));
                } while (v < target && ++guard < (1L << 31));
            }
            __syncthreads();
            {
                const uint4* src = reinterpret_cast<const uint4*>(g_hb);
                for (int q = tid; q < 4096; q += 256) {
                    int row = q >> 6, g = q & 63;
                    *reinterpret_cast<uint4*>(hS + row * HSTR + g * 8) = ldcg_v4(src + row * 64 + g);
                }
            }
            __syncthreads();
            float acc[2][4] = {};
#pragma unroll 4
            for (int ks = 0; ks < 512; ks += 16) {
                const __nv_bfloat16* ap = hS + (mrow + gid) * HSTR + ks + tig * 2;
                uint32_t a0 = *reinterpret_cast<const uint32_t*>(ap);
                uint32_t a1 = *reinterpret_cast<const uint32_t*>(ap + 8 * HSTR);
                uint32_t a2 = *reinterpret_cast<const uint32_t*>(ap + 8);
                uint32_t a3 = *reinterpret_cast<const uint32_t*>(ap + 8 * HSTR + 8);
#pragma unroll
                for (int nt = 0; nt < 2; nt++) {
                    const __nv_bfloat16* bp = wS + (ncol + nt * 8 + gid) * HSTR + ks + tig * 2;
                    uint32_t b0 = *reinterpret_cast<const uint32_t*>(bp);
                    uint32_t b1 = *reinterpret_cast<const uint32_t*>(bp + 8);
                    mma16816(acc[nt], a0, a1, a2, a3, b0, b1);
                }
            }
#pragma unroll
            for (int nt = 0; nt < 2; nt++) {
                int r0 = mrow + gid;
                int c = ncol + nt * 8 + tig * 2;
                gS[r0 * 33 + c]           = acc[nt][0];
                gS[r0 * 33 + c + 1]       = acc[nt][1];
                gS[(r0 + 8) * 33 + c]     = acc[nt][2];
                gS[(r0 + 8) * 33 + c + 1] = acc[nt][3];
            }
            __syncthreads();
        }

#pragma unroll
        for (int e = tid; e < 512; e += 256) {
            int b = e >> 3, jl = e & 7;
            int r = c0 + jl;
            const float* gxp = g_gx + ((size_t)t * BB + b) * G4;
            float gi = gxp[r], gf = gxp[512 + r], gg = gxp[1024 + r], go = gxp[1536 + r];
            if (t > 0) {
                gi += gS[b * 33 + jl];
                gf += gS[b * 33 + 8 + jl];
                gg += gS[b * 33 + 16 + jl];
                go += gS[b * 33 + 24 + jl];
            }
            int id = b * DR + r;
            float c = (t > 0) ? g_c[id] : 0.f;
            float cn = sigmoidf_(gf) * c + sigmoidf_(gi) * tanhf(gg);
            float hn = sigmoidf_(go) * tanhf(cn);
            g_c[id] = cn;
            g_hb[id] = __float2bfloat16(hn);
            g_hs8[(size_t)t * BB * DR + id] =
                __nv_cvt_float_to_fp8(hn * 64.f, __NV_SATFINITE, __NV_E4M3);
        }
        __syncthreads();
        if (tid == 0) {
            __threadfence();
            atomicAdd(&g_cnt, 1);
        }
    }
}

// ================= bf16 mma GEMM (gates_x), K=512 =================
#define SP 40
#define LG_DSMEM (128 * 132 * 4)

__global__ void __launch_bounds__(256) bmma_gates(const __nv_bfloat16* __restrict__ Abm,
                                                  const __nv_bfloat16* __restrict__ Bbm,
                                                  const float* __restrict__ bias,
                                                  float* __restrict__ Cp) {
    extern __shared__ char smem[];
    __nv_bfloat16* Asp = reinterpret_cast<__nv_bfloat16*>(smem);
    __nv_bfloat16* Bsp = reinterpret_cast<__nv_bfloat16*>(smem + 10240);
    const int tid = threadIdx.x, wid = tid >> 5, lid = tid & 31;
    const int gid = lid >> 2, tig = lid & 3;
    const int n0 = blockIdx.x * 128;
    const int m0 = blockIdx.y * 128;
    const int wm = (wid >> 2) * 64;
    const int wn = (wid & 3) * 32;
    const int NT = G4;

    float acc[4][4][4];
#pragma unroll
    for (int i = 0; i < 4; i++)
#pragma unroll
        for (int j = 0; j < 4; j++)
#pragma unroll
            for (int r = 0; r < 4; r++) acc[i][j][r] = 0.f;

    const int li0 = tid * 2, li1 = tid * 2 + 1;
    const int ar0 = li0 >> 2, ag0 = li0 & 3, ar1 = li1 >> 2, ag1 = li1 & 3;

    uint4 pa0, pa1, pb0, pb1;
    pa0 = *reinterpret_cast<const uint4*>(Abm + (size_t)(m0 + ar0) * DIN + ag0 * 8);
    pa1 = *reinterpret_cast<const uint4*>(Abm + (size_t)(m0 + ar1) * DIN + ag1 * 8);
    pb0 = *reinterpret_cast<const uint4*>(Bbm + (size_t)(n0 + ar0) * DIN + ag0 * 8);
    pb1 = *reinterpret_cast<const uint4*>(Bbm + (size_t)(n0 + ar1) * DIN + ag1 * 8);

    for (int kt = 0; kt < 16; kt++) {
        __syncthreads();
        *reinterpret_cast<uint4*>(Asp + ar0 * SP + ag0 * 8) = pa0;
        *reinterpret_cast<uint4*>(Asp + ar1 * SP + ag1 * 8) = pa1;
        *reinterpret_cast<uint4*>(Bsp + ar0 * SP + ag0 * 8) = pb0;
        *reinterpret_cast<uint4*>(Bsp + ar1 * SP + ag1 * 8) = pb1;
        __syncthreads();
        if (kt < 15) {
            int k0 = (kt + 1) * 32;
            pa0 = *reinterpret_cast<const uint4*>(Abm + (size_t)(m0 + ar0) * DIN + k0 + ag0 * 8);
            pa1 = *reinterpret_cast<const uint4*>(Abm + (size_t)(m0 + ar1) * DIN + k0 + ag1 * 8);
            pb0 = *reinterpret_cast<const uint4*>(Bbm + (size_t)(n0 + ar0) * DIN + k0 + ag0 * 8);
            pb1 = *reinterpret_cast<const uint4*>(Bbm + (size_t)(n0 + ar1) * DIN + k0 + ag1 * 8);
        }
#pragma unroll
        for (int ks = 0; ks < 32; ks += 16) {
            uint32_t af[4][4], bf[4][2];
#pragma unroll
            for (int mt = 0; mt < 4; mt++) {
                int r = wm + mt * 16 + gid;
                int k = ks + tig * 2;
                af[mt][0] = *reinterpret_cast<const uint32_t*>(Asp + r * SP + k);
                af[mt][1] = *reinterpret_cast<const uint32_t*>(Asp + (r + 8) * SP + k);
                af[mt][2] = *reinterpret_cast<const uint32_t*>(Asp + r * SP + k + 8);
                af[mt][3] = *reinterpret_cast<const uint32_t*>(Asp + (r + 8) * SP + k + 8);
            }
#pragma unroll
            for (int nt = 0; nt < 4; nt++) {
                int n = wn + nt * 8 + gid;
                int k = ks + tig * 2;
                bf[nt][0] = *reinterpret_cast<const uint32_t*>(Bsp + n * SP + k);
                bf[nt][1] = *reinterpret_cast<const uint32_t*>(Bsp + n * SP + k + 8);
            }
#pragma unroll
            for (int mt = 0; mt < 4; mt++)
#pragma unroll
                for (int nt = 0; nt < 4; nt++)
                    mma16816(acc[mt][nt], af[mt][0], af[mt][1], af[mt][2], af[mt][3],
                             bf[nt][0], bf[nt][1]);
        }
    }

    __syncthreads();
    float* stg = reinterpret_cast<float*>(smem);
#pragma unroll
    for (int mt = 0; mt < 4; mt++) {
#pragma unroll
        for (int nt = 0; nt < 4; nt++) {
            int r = wm + mt * 16 + gid;
            int c = wn + nt * 8 + tig * 2;
            int n = n0 + c;
            float bv0 = bias[n], bv1 = bias[n + 1];
            stg[r * 132 + c]           = acc[mt][nt][0] + bv0;
            stg[r * 132 + c + 1]       = acc[mt][nt][1] + bv1;
            stg[(r + 8) * 132 + c]     = acc[mt][nt][2] + bv0;
            stg[(r + 8) * 132 + c + 1] = acc[mt][nt][3] + bv1;
        }
    }
    __syncthreads();
    for (int row = wid; row < 128; row += 8) {
        int m = m0 + row;
        float* op = Cp + (size_t)m * NT + n0;
        for (int c = lid; c < 128; c += 32) op[c] = stg[row * 132 + c];
    }
}

// ================= fp8 logits GEMM (m16n8k32 e4m3), K=512 =================
// CTA tile 128x128; smem rows 80B (conflict-free for tig*4 pattern); 8 chunks of 64B.
#define SP8 80

__global__ void __launch_bounds__(256) bmma_logits8(const unsigned char* __restrict__ A8,
                                                    const unsigned char* __restrict__ B8,
                                                    const float* __restrict__ bias,
                                                    __nv_bfloat16* __restrict__ Cp) {
    extern __shared__ char smem[];
    unsigned char* Asp = reinterpret_cast<unsigned char*>(smem);           // 128*80 = 10240
    unsigned char* Bsp = reinterpret_cast<unsigned char*>(smem) + 10240;   // 10240
    const int tid = threadIdx.x, wid = tid >> 5, lid = tid & 31;
    const int gid = lid >> 2, tig = lid & 3;
    const int n0 = blockIdx.x * 128;
    const int m0 = blockIdx.y * 128;
    const int wm = (wid >> 2) * 64;
    const int wn = (wid & 3) * 32;

    float acc[4][4][4];
#pragma unroll
    for (int i = 0; i < 4; i++)
#pragma unroll
        for (int j = 0; j < 4; j++)
#pragma unroll
            for (int r = 0; r < 4; r++) acc[i][j][r] = 0.f;

    // loaders: li in [0,512): row = li>>2, seg = li&3 (16B each of a 64B chunk)
    const int li0 = tid * 2, li1 = tid * 2 + 1;
    const int ar0 = li0 >> 2, ag0 = li0 & 3, ar1 = li1 >> 2, ag1 = li1 & 3;
    int bn0 = n0 + ar0; if (bn0 > VOCAB1 - 1) bn0 = VOCAB1 - 1;
    int bn1 = n0 + ar1; if (bn1 > VOCAB1 - 1) bn1 = VOCAB1 - 1;

    uint4 pa0, pa1, pb0, pb1;
    pa0 = *reinterpret_cast<const uint4*>(A8 + (size_t)(m0 + ar0) * DIN + ag0 * 16);
    pa1 = *reinterpret_cast<const uint4*>(A8 + (size_t)(m0 + ar1) * DIN + ag1 * 16);
    pb0 = *reinterpret_cast<const uint4*>(B8 + (size_t)bn0 * DIN + ag0 * 16);
    pb1 = *reinterpret_cast<const uint4*>(B8 + (size_t)bn1 * DIN + ag1 * 16);

    for (int kc = 0; kc < 8; kc++) {
        __syncthreads();
        *reinterpret_cast<uint4*>(Asp + ar0 * SP8 + ag0 * 16) = pa0;
        *reinterpret_cast<uint4*>(Asp + ar1 * SP8 + ag1 * 16) = pa1;
        *reinterpret_cast<uint4*>(Bsp + ar0 * SP8 + ag0 * 16) = pb0;
        *reinterpret_cast<uint4*>(Bsp + ar1 * SP8 + ag1 * 16) = pb1;
        __syncthreads();
        if (kc < 7) {
            int k0 = (kc + 1) * 64;
            pa0 = *reinterpret_cast<const uint4*>(A8 + (size_t)(m0 + ar0) * DIN + k0 + ag0 * 16);
            pa1 = *reinterpret_cast<const uint4*>(A8 + (size_t)(m0 + ar1) * DIN + k0 + ag1 * 16);
            pb0 = *reinterpret_cast<const uint4*>(B8 + (size_t)bn0 * DIN + k0 + ag0 * 16);
            pb1 = *reinterpret_cast<const uint4*>(B8 + (size_t)bn1 * DIN + k0 + ag1 * 16);
        }
#pragma unroll
        for (int ks = 0; ks < 64; ks += 32) {
            uint32_t af[4][4], bf[4][2];
#pragma unroll
            for (int mt = 0; mt < 4; mt++) {
                int r = wm + mt * 16 + gid;
                const unsigned char* ap = Asp + r * SP8 + ks + tig * 4;
                af[mt][0] = *reinterpret_cast<const uint32_t*>(ap);
                af[mt][1] = *reinterpret_cast<const uint32_t*>(ap + 8 * SP8);
                af[mt][2] = *reinterpret_cast<const uint32_t*>(ap + 16);
                af[mt][3] = *reinterpret_cast<const uint32_t*>(ap + 8 * SP8 + 16);
            }
#pragma unroll
            for (int nt = 0; nt < 4; nt++) {
                int n = wn + nt * 8 + gid;
                const unsigned char* bp = Bsp + n * SP8 + ks + tig * 4;
                bf[nt][0] = *reinterpret_cast<const uint32_t*>(bp);
                bf[nt][1] = *reinterpret_cast<const uint32_t*>(bp + 16);
            }
#pragma unroll
            for (int mt = 0; mt < 4; mt++)
#pragma unroll
                for (int nt = 0; nt < 4; nt++)
                    mma_fp8(acc[mt][nt], af[mt][0], af[mt][1], af[mt][2], af[mt][3],
                            bf[nt][0], bf[nt][1]);
        }
    }

    // epilogue: scale 1/4096, +bias, stage, remap + bf16 out + partial lse
    __syncthreads();
    float* stg = reinterpret_cast<float*>(smem);
    const float SC = 1.f / 4096.f;
#pragma unroll
    for (int mt = 0; mt < 4; mt++) {
#pragma unroll
        for (int nt = 0; nt < 4; nt++) {
            int r = wm + mt * 16 + gid;
            int c = wn + nt * 8 + tig * 2;
            int n = n0 + c;
            int ncl = (n > VOCAB1 - 1) ? VOCAB1 - 1 : n;
            int ncl1 = (n + 1 > VOCAB1 - 1) ? VOCAB1 - 1 : n + 1;
            float bv0 = bias[ncl], bv1 = bias[ncl1];
            stg[r * 132 + c]           = acc[mt][nt][0] * SC + bv0;
            stg[r * 132 + c + 1]       = acc[mt][nt][1] * SC + bv1;
            stg[(r + 8) * 132 + c]     = acc[mt][nt][2] * SC + bv0;
            stg[(r + 8) * 132 + c + 1] = acc[mt][nt][3] * SC + bv1;
        }
    }
    __syncthreads();
    int nmax = VOCAB1 - n0;
    if (nmax > 128) nmax = 128;
    for (int row = wid; row < 128; row += 8) {
        int m = m0 + row;
        int t = m >> 6, b = m & 63;
        int r_out = b * TT + t;
        __nv_bfloat16* op = Cp + (size_t)r_out * VP + n0;
        float v0 = -INFINITY, v1 = -INFINITY, v2 = -INFINITY, v3 = -INFINITY;
        int c0 = lid, c1 = lid + 32, c2 = lid + 64, c3 = lid + 96;
        if (c0 < nmax) { v0 = stg[row * 132 + c0]; op[c0] = __float2bfloat16(v0); }
        if (c1 < nmax) { v1 = stg[row * 132 + c1]; op[c1] = __float2bfloat16(v1); }
        if (c2 < nmax) { v2 = stg[row * 132 + c2]; op[c2] = __float2bfloat16(v2); }
        if (c3 < nmax) { v3 = stg[row * 132 + c3]; op[c3] = __float2bfloat16(v3); }
        float mx = fmaxf(fmaxf(v0, v1), fmaxf(v2, v3));
#pragma unroll
        for (int o = 16; o > 0; o >>= 1)
            mx = fmaxf(mx, __shfl_xor_sync(0xffffffffu, mx, o));
        float s = 0.f;
        if (c0 < nmax) s += __expf(v0 - mx);
        if (c1 < nmax) s += __expf(v1 - mx);
        if (c2 < nmax) s += __expf(v2 - mx);
        if (c3 < nmax) s += __expf(v3 - mx);
#pragma unroll
        for (int o = 16; o > 0; o >>= 1)
            s += __shfl_xor_sync(0xffffffffu, s, o);
        if (lid == 0) {
            g_pmax[(size_t)r_out * NBLK_LG + blockIdx.x] = mx;
            g_psum[(size_t)r_out * NBLK_LG + blockIdx.x] = s;
        }
    }
}

// ================= lse reduce + final output =================
__global__ void lse_reduce() {
    int row = blockIdx.x * 8 + (threadIdx.x >> 5);
    int lid = threadIdx.x & 31;
    float m = -INFINITY, s = 0.f;
    for (int i = lid; i < NBLK_LG; i += 32) {
        float m2 = g_pmax[(size_t)row * NBLK_LG + i];
        float s2 = g_psum[(size_t)row * NBLK_LG + i];
        if (m2 > m) { s = s * __expf(m - m2) + s2; m = m2; }
        else        { s += s2 * __expf(m2 - m); }
    }
#pragma unroll
    for (int o = 16; o > 0; o >>= 1) {
        float m2 = __shfl_xor_sync(0xffffffffu, m, o);
        float s2 = __shfl_xor_sync(0xffffffffu, s, o);
        if (m2 > m) { s = s * __expf(m - m2) + s2; m = m2; }
        else        { s += s2 * __expf(m2 - m); }
    }
    if (lid == 0) g_lse[row] = m + logf(s);
}

__global__ void final_out(float* __restrict__ out) {
    int row = blockIdx.y;
    int v = (blockIdx.x * 256 + threadIdx.x) * 4;
    float l = g_lse[row];
    const __nv_bfloat16* lp = g_lgb + (size_t)row * VP;
    float* op = out + (size_t)row * VOCAB1;
    if (v + 3 < VOCAB1) {
        uint2 u = *reinterpret_cast<const uint2*>(lp + v);
        __nv_bfloat162 p0 = *reinterpret_cast<__nv_bfloat162*>(&u.x);
        __nv_bfloat162 p1 = *reinterpret_cast<__nv_bfloat162*>(&u.y);
        op[v + 0] = __bfloat162float(p0.x) - l;
        op[v + 1] = __bfloat162float(p0.y) - l;
        op[v + 2] = __bfloat162float(p1.x) - l;
        op[v + 3] = __bfloat162float(p1.y) - l;
    } else {
        for (int j = v; j < VOCAB1; j++) op[j] = __bfloat162float(lp[j]) - l;
    }
}

// ================= launch =================
extern "C" void kernel_launch(void* const* d_in, const int* in_sizes, int n_in,
                              void* d_out, int out_size) {
    const float* img_feat = (const float*)d_in[0];
    const int*   seq      = (const int*)d_in[1];
    const float* W_img    = (const float*)d_in[2];
    const float* b_img    = (const float*)d_in[3];
    const float* embed    = (const float*)d_in[4];
    const float* W_ih     = (const float*)d_in[5];
    const float* b_ih     = (const float*)d_in[6];
    const float* W_hh     = (const float*)d_in[7];
    const float* b_hh     = (const float*)d_in[8];
    const float* W_logit  = (const float*)d_in[9];
    const float* b_logit  = (const float*)d_in[10];
    float* out = (float*)d_out;

    float *gx, *bias2;
    __nv_bfloat16 *xsb, *wib, *whb, *lgb;
    unsigned char *hs8, *wl8;
    cudaGetSymbolAddress((void**)&gx,    g_gx);
    cudaGetSymbolAddress((void**)&bias2, g_bias2);
    cudaGetSymbolAddress((void**)&xsb,   g_xsb);
    cudaGetSymbolAddress((void**)&wib,   g_wib);
    cudaGetSymbolAddress((void**)&whb,   g_whb);
    cudaGetSymbolAddress((void**)&lgb,   g_lgb);
    cudaGetSymbolAddress((void**)&hs8,   g_hs8);
    cudaGetSymbolAddress((void**)&wl8,   g_wl8);

    cudaFuncSetAttribute(bmma_gates,   cudaFuncAttributeMaxDynamicSharedMemorySize, LG_DSMEM);
    cudaFuncSetAttribute(bmma_logits8, cudaFuncAttributeMaxDynamicSharedMemorySize, LG_DSMEM);
    cudaFuncSetAttribute(lstm_persist64, cudaFuncAttributeMaxDynamicSharedMemorySize, ST_SMEM);

    init_k<<<128, 256>>>(b_ih, b_hh);
    gather_embed<<<dim3(19, 64), 128>>>(seq, embed);
    conv_fp8<<<((size_t)VOCAB1 * DR / 4 + 255) / 256, 256>>>(W_logit, wl8, (size_t)VOCAB1 * DR);
    conv_bf16<<<((size_t)G4 * DIN / 4 + 255) / 256, 256>>>(W_ih, wib, (size_t)G4 * DIN);
    conv_bf16<<<((size_t)G4 * DR / 4 + 255) / 256, 256>>>(W_hh, whb, (size_t)G4 * DR);

    x0_ksplit<<<dim3(8, 8), 256>>>(img_feat, W_img);
    x0_reduce<<<(BB * DIN) / 256, 256>>>(b_img);

    bmma_gates<<<dim3(16, 10), 256, LG_DSMEM>>>(xsb, wib, bias2, gx);

    lstm_persist64<<<64, 256, ST_SMEM>>>();

    bmma_logits8<<<dim3(NBLK_LG, 10), 256, LG_DSMEM>>>(hs8, wl8, b_logit, lgb);

    lse_reduce<<<BB * TT / 8, 256>>>();
    final_out<<<dim3(32, BB * TT), 256>>>(out);
}

// round 12
// speedup vs baseline: 3.5527x; 1.0132x over previous
#include <cuda_runtime.h>
#include <cuda_bf16.h>
#include <cuda_fp8.h>
#include <math.h>
#include <stdint.h>

#define VOCAB1 32001
#define VP     32004
#define DIN 512
#define DR  512
#define DF  2048
#define BB  64
#define TT  20
#define G4  2048
#define NBLK_LG 251

// ================= device scratch =================
__device__ __align__(16) __nv_bfloat16 g_xsb[TT * BB * DIN];
__device__ __align__(16) float g_gx[(size_t)TT * BB * G4];
__device__ __align__(16) float g_c[BB * DR];
__device__ __align__(16) __nv_bfloat16 g_hb[BB * DR];
__device__ __align__(16) unsigned char g_hs8[TT * BB * DR];
__device__ __align__(16) unsigned char g_wl8[(size_t)VOCAB1 * DR];
__device__ __align__(16) __nv_bfloat16 g_wib[(size_t)G4 * DIN];
__device__ __align__(16) __nv_bfloat16 g_whb[(size_t)G4 * DR];
__device__ __align__(16) float g_bias2[G4];
__device__ __align__(16) float g_lse[BB * TT];
__device__ __align__(16) float g_x0p[8 * BB * DIN];
__device__ __align__(16) float g_pmax[BB * TT * NBLK_LG];
__device__ __align__(16) float g_psum[BB * TT * NBLK_LG];
__device__ __align__(16) __nv_bfloat16 g_lgb[(size_t)BB * TT * VP];
__device__ int g_cnt;

// ================= fused init + embedding gather =================
// grid: 1216 blocks x 128 threads. Block bid -> gather (t=1+bid/64, b=bid%64).
// All threads also cover init work by global id.
__global__ void init_gather(const int* __restrict__ seq, const float* __restrict__ embed,
                            const float* __restrict__ b_ih, const float* __restrict__ b_hh) {
    int bid = blockIdx.x, tid = threadIdx.x;
    int id = bid * 128 + tid;
    if (id < BB * DR) g_c[id] = 0.f;
    if (id < G4) g_bias2[id] = b_ih[id] + b_hh[id];
    if (id == 0) g_cnt = 0;

    int t = 1 + (bid >> 6), b = bid & 63;
    int idx = seq[b * TT + t];
    if (idx < 0) idx = 0;
    if (idx > VOCAB1 - 1) idx = VOCAB1 - 1;
    float4 v = reinterpret_cast<const float4*>(embed + (size_t)idx * DIN)[tid];
    __nv_bfloat162 p0 = __floats2bfloat162_rn(v.x, v.y);
    __nv_bfloat162 p1 = __floats2bfloat162_rn(v.z, v.w);
    uint2 u;
    u.x = *reinterpret_cast<uint32_t*>(&p0);
    u.y = *reinterpret_cast<uint32_t*>(&p1);
    reinterpret_cast<uint2*>(g_xsb + ((size_t)t * BB + b) * DIN)[tid] = u;
}

// ================= fused weight conversion (fp8 W_logit + bf16 W_ih/W_hh) =================
#define NQ_WL ((size_t)VOCAB1 * DR / 4)    // 4096128
#define NQ_WI ((size_t)G4 * DIN / 4)       // 262144
#define NQ_WH ((size_t)G4 * DR / 4)        // 262144
__global__ void conv_all(const float* __restrict__ wl, const float* __restrict__ wi,
                         const float* __restrict__ wh) {
    size_t q = (size_t)blockIdx.x * blockDim.x + threadIdx.x;
    if (q < NQ_WL) {
        size_t i = q * 4;
        float4 v = *reinterpret_cast<const float4*>(wl + i);
        uint32_t r =
            (uint32_t)__nv_cvt_float_to_fp8(v.x * 64.f, __NV_SATFINITE, __NV_E4M3)
          | ((uint32_t)__nv_cvt_float_to_fp8(v.y * 64.f, __NV_SATFINITE, __NV_E4M3) << 8)
          | ((uint32_t)__nv_cvt_float_to_fp8(v.z * 64.f, __NV_SATFINITE, __NV_E4M3) << 16)
          | ((uint32_t)__nv_cvt_float_to_fp8(v.w * 64.f, __NV_SATFINITE, __NV_E4M3) << 24);
        *reinterpret_cast<uint32_t*>(g_wl8 + i) = r;
        return;
    }
    q -= NQ_WL;
    const float* src;
    __nv_bfloat16* dst;
    if (q < NQ_WI) { src = wi; dst = g_wib; }
    else if (q < NQ_WI + NQ_WH) { q -= NQ_WI; src = wh; dst = g_whb; }
    else return;
    size_t i = q * 4;
    float4 v = *reinterpret_cast<const float4*>(src + i);
    __nv_bfloat162 p0 = __floats2bfloat162_rn(v.x, v.y);
    __nv_bfloat162 p1 = __floats2bfloat162_rn(v.z, v.w);
    uint2 u;
    u.x = *reinterpret_cast<uint32_t*>(&p0);
    u.y = *reinterpret_cast<uint32_t*>(&p1);
    *reinterpret_cast<uint2*>(&dst[i]) = u;
}
#define CONV_BLOCKS ((int)((NQ_WL + NQ_WI + NQ_WH + 255) / 256))

// ================= x0: k-split fp32 GEMM =================
__global__ void x0_ksplit(const float* __restrict__ A, const float* __restrict__ Bm) {
    __shared__ float As[16][64];
    __shared__ float Bs[16][64];
    const int tid = threadIdx.x;
    const int n0 = blockIdx.x * 64;
    const int kbeg = blockIdx.y * 256;
    const int tx = tid & 15, ty = tid >> 4;
    float acc[4][4] = {};
    for (int kt = 0; kt < 256; kt += 16) {
        {
            int row = tid >> 2, kq = (tid & 3) << 2;
            float4 v = *reinterpret_cast<const float4*>(A + (size_t)row * DF + kbeg + kt + kq);
            As[kq + 0][row] = v.x; As[kq + 1][row] = v.y;
            As[kq + 2][row] = v.z; As[kq + 3][row] = v.w;
        }
        {
            int row = tid >> 2, kq = (tid & 3) << 2;
            float4 v = *reinterpret_cast<const float4*>(Bm + (size_t)(n0 + row) * DF + kbeg + kt + kq);
            Bs[kq + 0][row] = v.x; Bs[kq + 1][row] = v.y;
            Bs[kq + 2][row] = v.z; Bs[kq + 3][row] = v.w;
        }
        __syncthreads();
#pragma unroll
        for (int k = 0; k < 16; k++) {
            float a[4], b[4];
#pragma unroll
            for (int i = 0; i < 4; i++) a[i] = As[k][ty * 4 + i];
#pragma unroll
            for (int j = 0; j < 4; j++) b[j] = Bs[k][tx * 4 + j];
#pragma unroll
            for (int i = 0; i < 4; i++)
#pragma unroll
                for (int j = 0; j < 4; j++) acc[i][j] = fmaf(a[i], b[j], acc[i][j]);
        }
        __syncthreads();
    }
    float* p = g_x0p + (size_t)blockIdx.y * BB * DIN;
#pragma unroll
    for (int i = 0; i < 4; i++)
#pragma unroll
        for (int j = 0; j < 4; j++)
            p[(ty * 4 + i) * DIN + n0 + tx * 4 + j] = acc[i][j];
}

__global__ void x0_reduce(const float* __restrict__ b_img) {
    int id = blockIdx.x * blockDim.x + threadIdx.x;
    float s = b_img[id & 511];
#pragma unroll
    for (int kb = 0; kb < 8; kb++) s += g_x0p[kb * BB * DIN + id];
    g_xsb[id] = __float2bfloat16(s);
}

// ================= mma primitives =================
__device__ __forceinline__ void mma16816(float* d, uint32_t a0, uint32_t a1,
                                         uint32_t a2, uint32_t a3,
                                         uint32_t b0, uint32_t b1) {
    asm volatile(
        "mma.sync.aligned.m16n8k16.row.col.f32.bf16.bf16.f32 "
        "{%0,%1,%2,%3}, {%4,%5,%6,%7}, {%8,%9}, {%0,%1,%2,%3};"
        : "+f"(d[0]), "+f"(d[1]), "+f"(d[2]), "+f"(d[3])
        : "r"(a0), "r"(a1), "r"(a2), "r"(a3), "r"(b0), "r"(b1));
}

__device__ __forceinline__ void mma_fp8(float* d, uint32_t a0, uint32_t a1,
                                        uint32_t a2, uint32_t a3,
                                        uint32_t b0, uint32_t b1) {
    asm volatile(
        "mma.sync.aligned.m16n8k32.row.col.f32.e4m3.e4m3.f32 "
        "{%0,%1,%2,%3}, {%4,%5,%6,%7}, {%8,%9}, {%0,%1,%2,%3};"
        : "+f"(d[0]), "+f"(d[1]), "+f"(d[2]), "+f"(d[3])
        : "r"(a0), "r"(a1), "r"(a2), "r"(a3), "r"(b0), "r"(b1));
}

__device__ __forceinline__ float sigmoidf_(float x) { return 1.f / (1.f + __expf(-x)); }

__device__ __forceinline__ uint4 ldcg_v4(const uint4* p) {
    uint4 v;
    asm volatile("ld.global.cg.v4.u32 {%0,%1,%2,%3}, [%4];"
                 : "=r"(v.x), "=r"(v.y), "=r"(v.z), "=r"(v.w) : "l"(p));
    return v;
}

// ================= persistent LSTM (64 CTAs, single launch) =================
#define HSTR 520
#define ST_SMEM (64 * HSTR * 2 + 32 * HSTR * 2 + 64 * 33 * 4)

__global__ void __launch_bounds__(256) lstm_persist64() {
    extern __shared__ char smem[];
    __nv_bfloat16* hS = reinterpret_cast<__nv_bfloat16*>(smem);
    __nv_bfloat16* wS = reinterpret_cast<__nv_bfloat16*>(smem + 64 * HSTR * 2);
    float* gS = reinterpret_cast<float*>(smem + 64 * HSTR * 2 + 32 * HSTR * 2);
    const int tid = threadIdx.x, wid = tid >> 5, lid = tid & 31;
    const int gid = lid >> 2, tig = lid & 3;
    const int cta = blockIdx.x;
    const int c0 = cta * 8;

    for (int q = tid; q < 2048; q += 256) {
        int j = q >> 6, g = q & 63;
        int wr = (j >> 3) * 512 + c0 + (j & 7);
        *reinterpret_cast<uint4*>(wS + j * HSTR + g * 8) =
            reinterpret_cast<const uint4*>(g_whb + (size_t)wr * DR)[g];
    }
    __syncthreads();

    const int mrow = (wid >> 1) * 16;
    const int ncol = (wid & 1) * 16;

    for (int t = 0; t < TT; t++) {
        if (t > 0) {
            if (tid == 0) {
                int target = 64 * t, v;
                long guard = 0;
                do {
                    asm volatile("ld.global.cg.s32 %0, [%1];" : "=r"(v) : "l"(&g_cnt));
                } while (v < target && ++guard < (1L << 31));
            }
            __syncthreads();
            {
                const uint4* src = reinterpret_cast<const uint4*>(g_hb);
                for (int q = tid; q < 4096; q += 256) {
                    int row = q >> 6, g = q & 63;
                    *reinterpret_cast<uint4*>(hS + row * HSTR + g * 8) = ldcg_v4(src + row * 64 + g);
                }
            }
            __syncthreads();
            float acc[2][4] = {};
#pragma unroll 4
            for (int ks = 0; ks < 512; ks += 16) {
                const __nv_bfloat16* ap = hS + (mrow + gid) * HSTR + ks + tig * 2;
                uint32_t a0 = *reinterpret_cast<const uint32_t*>(ap);
                uint32_t a1 = *reinterpret_cast<const uint32_t*>(ap + 8 * HSTR);
                uint32_t a2 = *reinterpret_cast<const uint32_t*>(ap + 8);
                uint32_t a3 = *reinterpret_cast<const uint32_t*>(ap + 8 * HSTR + 8);
#pragma unroll
                for (int nt = 0; nt < 2; nt++) {
                    const __nv_bfloat16* bp = wS + (ncol + nt * 8 + gid) * HSTR + ks + tig * 2;
                    uint32_t b0 = *reinterpret_cast<const uint32_t*>(bp);
                    uint32_t b1 = *reinterpret_cast<const uint32_t*>(bp + 8);
                    mma16816(acc[nt], a0, a1, a2, a3, b0, b1);
                }
            }
#pragma unroll
            for (int nt = 0; nt < 2; nt++) {
                int r0 = mrow + gid;
                int c = ncol + nt * 8 + tig * 2;
                gS[r0 * 33 + c]           = acc[nt][0];
                gS[r0 * 33 + c + 1]       = acc[nt][1];
                gS[(r0 + 8) * 33 + c]     = acc[nt][2];
                gS[(r0 + 8) * 33 + c + 1] = acc[nt][3];
            }
            __syncthreads();
        }

#pragma unroll
        for (int e = tid; e < 512; e += 256) {
            int b = e >> 3, jl = e & 7;
            int r = c0 + jl;
            const float* gxp = g_gx + ((size_t)t * BB + b) * G4;
            float gi = gxp[r], gf = gxp[512 + r], gg = gxp[1024 + r], go = gxp[1536 + r];
            if (t > 0) {
                gi += gS[b * 33 + jl];
                gf += gS[b * 33 + 8 + jl];
                gg += gS[b * 33 + 16 + jl];
                go += gS[b * 33 + 24 + jl];
            }
            int id = b * DR + r;
            float c = (t > 0) ? g_c[id] : 0.f;
            float cn = sigmoidf_(gf) * c + sigmoidf_(gi) * tanhf(gg);
            float hn = sigmoidf_(go) * tanhf(cn);
            g_c[id] = cn;
            g_hb[id] = __float2bfloat16(hn);
            g_hs8[(size_t)t * BB * DR + id] =
                __nv_cvt_float_to_fp8(hn * 64.f, __NV_SATFINITE, __NV_E4M3);
        }
        __syncthreads();
        if (tid == 0) {
            __threadfence();
            atomicAdd(&g_cnt, 1);
        }
    }
}

// ================= bf16 mma GEMM (gates_x), K=512 =================
#define SP 40
#define LG_DSMEM (128 * 132 * 4)

__global__ void __launch_bounds__(256) bmma_gates(const __nv_bfloat16* __restrict__ Abm,
                                                  const __nv_bfloat16* __restrict__ Bbm,
                                                  const float* __restrict__ bias,
                                                  float* __restrict__ Cp) {
    extern __shared__ char smem[];
    __nv_bfloat16* Asp = reinterpret_cast<__nv_bfloat16*>(smem);
    __nv_bfloat16* Bsp = reinterpret_cast<__nv_bfloat16*>(smem + 10240);
    const int tid = threadIdx.x, wid = tid >> 5, lid = tid & 31;
    const int gid = lid >> 2, tig = lid & 3;
    const int n0 = blockIdx.x * 128;
    const int m0 = blockIdx.y * 128;
    const int wm = (wid >> 2) * 64;
    const int wn = (wid & 3) * 32;
    const int NT = G4;

    float acc[4][4][4];
#pragma unroll
    for (int i = 0; i < 4; i++)
#pragma unroll
        for (int j = 0; j < 4; j++)
#pragma unroll
            for (int r = 0; r < 4; r++) acc[i][j][r] = 0.f;

    const int li0 = tid * 2, li1 = tid * 2 + 1;
    const int ar0 = li0 >> 2, ag0 = li0 & 3, ar1 = li1 >> 2, ag1 = li1 & 3;

    uint4 pa0, pa1, pb0, pb1;
    pa0 = *reinterpret_cast<const uint4*>(Abm + (size_t)(m0 + ar0) * DIN + ag0 * 8);
    pa1 = *reinterpret_cast<const uint4*>(Abm + (size_t)(m0 + ar1) * DIN + ag1 * 8);
    pb0 = *reinterpret_cast<const uint4*>(Bbm + (size_t)(n0 + ar0) * DIN + ag0 * 8);
    pb1 = *reinterpret_cast<const uint4*>(Bbm + (size_t)(n0 + ar1) * DIN + ag1 * 8);

    for (int kt = 0; kt < 16; kt++) {
        __syncthreads();
        *reinterpret_cast<uint4*>(Asp + ar0 * SP + ag0 * 8) = pa0;
        *reinterpret_cast<uint4*>(Asp + ar1 * SP + ag1 * 8) = pa1;
        *reinterpret_cast<uint4*>(Bsp + ar0 * SP + ag0 * 8) = pb0;
        *reinterpret_cast<uint4*>(Bsp + ar1 * SP + ag1 * 8) = pb1;
        __syncthreads();
        if (kt < 15) {
            int k0 = (kt + 1) * 32;
            pa0 = *reinterpret_cast<const uint4*>(Abm + (size_t)(m0 + ar0) * DIN + k0 + ag0 * 8);
            pa1 = *reinterpret_cast<const uint4*>(Abm + (size_t)(m0 + ar1) * DIN + k0 + ag1 * 8);
            pb0 = *reinterpret_cast<const uint4*>(Bbm + (size_t)(n0 + ar0) * DIN + k0 + ag0 * 8);
            pb1 = *reinterpret_cast<const uint4*>(Bbm + (size_t)(n0 + ar1) * DIN + k0 + ag1 * 8);
        }
#pragma unroll
        for (int ks = 0; ks < 32; ks += 16) {
            uint32_t af[4][4], bf[4][2];
#pragma unroll
            for (int mt = 0; mt < 4; mt++) {
                int r = wm + mt * 16 + gid;
                int k = ks + tig * 2;
                af[mt][0] = *reinterpret_cast<const uint32_t*>(Asp + r * SP + k);
                af[mt][1] = *reinterpret_cast<const uint32_t*>(Asp + (r + 8) * SP + k);
                af[mt][2] = *reinterpret_cast<const uint32_t*>(Asp + r * SP + k + 8);
                af[mt][3] = *reinterpret_cast<const uint32_t*>(Asp + (r + 8) * SP + k + 8);
            }
#pragma unroll
            for (int nt = 0; nt < 4; nt++) {
                int n = wn + nt * 8 + gid;
                int k = ks + tig * 2;
                bf[nt][0] = *reinterpret_cast<const uint32_t*>(Bsp + n * SP + k);
                bf[nt][1] = *reinterpret_cast<const uint32_t*>(Bsp + n * SP + k + 8);
            }
#pragma unroll
            for (int mt = 0; mt < 4; mt++)
#pragma unroll
                for (int nt = 0; nt < 4; nt++)
                    mma16816(acc[mt][nt], af[mt][0], af[mt][1], af[mt][2], af[mt][3],
                             bf[nt][0], bf[nt][1]);
        }
    }

    __syncthreads();
    float* stg = reinterpret_cast<float*>(smem);
#pragma unroll
    for (int mt = 0; mt < 4; mt++) {
#pragma unroll
        for (int nt = 0; nt < 4; nt++) {
            int r = wm + mt * 16 + gid;
            int c = wn + nt * 8 + tig * 2;
            int n = n0 + c;
            float bv0 = bias[n], bv1 = bias[n + 1];
            stg[r * 132 + c]           = acc[mt][nt][0] + bv0;
            stg[r * 132 + c + 1]       = acc[mt][nt][1] + bv1;
            stg[(r + 8) * 132 + c]     = acc[mt][nt][2] + bv0;
            stg[(r + 8) * 132 + c + 1] = acc[mt][nt][3] + bv1;
        }
    }
    __syncthreads();
    for (int row = wid; row < 128; row += 8) {
        int m = m0 + row;
        float* op = Cp + (size_t)m * NT + n0;
        for (int c = lid; c < 128; c += 32) op[c] = stg[row * 132 + c];
    }
}

// ================= fp8 logits GEMM (m16n8k32 e4m3), K=512 =================
#define SP8 80

__global__ void __launch_bounds__(256) bmma_logits8(const unsigned char* __restrict__ A8,
                                                    const unsigned char* __restrict__ B8,
                                                    const float* __restrict__ bias,
                                                    __nv_bfloat16* __restrict__ Cp) {
    extern __shared__ char smem[];
    unsigned char* Asp = reinterpret_cast<unsigned char*>(smem);
    unsigned char* Bsp = reinterpret_cast<unsigned char*>(smem) + 10240;
    const int tid = threadIdx.x, wid = tid >> 5, lid = tid & 31;
    const int gid = lid >> 2, tig = lid & 3;
    const int n0 = blockIdx.x * 128;
    const int m0 = blockIdx.y * 128;
    const int wm = (wid >> 2) * 64;
    const int wn = (wid & 3) * 32;

    float acc[4][4][4];
#pragma unroll
    for (int i = 0; i < 4; i++)
#pragma unroll
        for (int j = 0; j < 4; j++)
#pragma unroll
            for (int r = 0; r < 4; r++) acc[i][j][r] = 0.f;

    const int li0 = tid * 2, li1 = tid * 2 + 1;
    const int ar0 = li0 >> 2, ag0 = li0 & 3, ar1 = li1 >> 2, ag1 = li1 & 3;
    int bn0 = n0 + ar0; if (bn0 > VOCAB1 - 1) bn0 = VOCAB1 - 1;
    int bn1 = n0 + ar1; if (bn1 > VOCAB1 - 1) bn1 = VOCAB1 - 1;

    uint4 pa0, pa1, pb0, pb1;
    pa0 = *reinterpret_cast<const uint4*>(A8 + (size_t)(m0 + ar0) * DIN + ag0 * 16);
    pa1 = *reinterpret_cast<const uint4*>(A8 + (size_t)(m0 + ar1) * DIN + ag1 * 16);
    pb0 = *reinterpret_cast<const uint4*>(B8 + (size_t)bn0 * DIN + ag0 * 16);
    pb1 = *reinterpret_cast<const uint4*>(B8 + (size_t)bn1 * DIN + ag1 * 16);

    for (int kc = 0; kc < 8; kc++) {
        __syncthreads();
        *reinterpret_cast<uint4*>(Asp + ar0 * SP8 + ag0 * 16) = pa0;
        *reinterpret_cast<uint4*>(Asp + ar1 * SP8 + ag1 * 16) = pa1;
        *reinterpret_cast<uint4*>(Bsp + ar0 * SP8 + ag0 * 16) = pb0;
        *reinterpret_cast<uint4*>(Bsp + ar1 * SP8 + ag1 * 16) = pb1;
        __syncthreads();
        if (kc < 7) {
            int k0 = (kc + 1) * 64;
            pa0 = *reinterpret_cast<const uint4*>(A8 + (size_t)(m0 + ar0) * DIN + k0 + ag0 * 16);
            pa1 = *reinterpret_cast<const uint4*>(A8 + (size_t)(m0 + ar1) * DIN + k0 + ag1 * 16);
            pb0 = *reinterpret_cast<const uint4*>(B8 + (size_t)bn0 * DIN + k0 + ag0 * 16);
            pb1 = *reinterpret_cast<const uint4*>(B8 + (size_t)bn1 * DIN + k0 + ag1 * 16);
        }
#pragma unroll
        for (int ks = 0; ks < 64; ks += 32) {
            uint32_t af[4][4], bf[4][2];
#pragma unroll
            for (int mt = 0; mt < 4; mt++) {
                int r = wm + mt * 16 + gid;
                const unsigned char* ap = Asp + r * SP8 + ks + tig * 4;
                af[mt][0] = *reinterpret_cast<const uint32_t*>(ap);
                af[mt][1] = *reinterpret_cast<const uint32_t*>(ap + 8 * SP8);
                af[mt][2] = *reinterpret_cast<const uint32_t*>(ap + 16);
                af[mt][3] = *reinterpret_cast<const uint32_t*>(ap + 8 * SP8 + 16);
            }
#pragma unroll
            for (int nt = 0; nt < 4; nt++) {
                int n = wn + nt * 8 + gid;
                const unsigned char* bp = Bsp + n * SP8 + ks + tig * 4;
                bf[nt][0] = *reinterpret_cast<const uint32_t*>(bp);
                bf[nt][1] = *reinterpret_cast<const uint32_t*>(bp + 16);
            }
#pragma unroll
            for (int mt = 0; mt < 4; mt++)
#pragma unroll
                for (int nt = 0; nt < 4; nt++)
                    mma_fp8(acc[mt][nt], af[mt][0], af[mt][1], af[mt][2], af[mt][3],
                            bf[nt][0], bf[nt][1]);
        }
    }

    __syncthreads();
    float* stg = reinterpret_cast<float*>(smem);
    const float SC = 1.f / 4096.f;
#pragma unroll
    for (int mt = 0; mt < 4; mt++) {
#pragma unroll
        for (int nt = 0; nt < 4; nt++) {
            int r = wm + mt * 16 + gid;
            int c = wn + nt * 8 + tig * 2;
            int n = n0 + c;
            int ncl = (n > VOCAB1 - 1) ? VOCAB1 - 1 : n;
            int ncl1 = (n + 1 > VOCAB1 - 1) ? VOCAB1 - 1 : n + 1;
            float bv0 = bias[ncl], bv1 = bias[ncl1];
            stg[r * 132 + c]           = acc[mt][nt][0] * SC + bv0;
            stg[r * 132 + c + 1]       = acc[mt][nt][1] * SC + bv1;
            stg[(r + 8) * 132 + c]     = acc[mt][nt][2] * SC + bv0;
            stg[(r + 8) * 132 + c + 1] = acc[mt][nt][3] * SC + bv1;
        }
    }
    __syncthreads();
    int nmax = VOCAB1 - n0;
    if (nmax > 128) nmax = 128;
    for (int row = wid; row < 128; row += 8) {
        int m = m0 + row;
        int t = m >> 6, b = m & 63;
        int r_out = b * TT + t;
        __nv_bfloat16* op = Cp + (size_t)r_out * VP + n0;
        float v0 = -INFINITY, v1 = -INFINITY, v2 = -INFINITY, v3 = -INFINITY;
        int c0 = lid, c1 = lid + 32, c2 = lid + 64, c3 = lid + 96;
        if (c0 < nmax) { v0 = stg[row * 132 + c0]; op[c0] = __float2bfloat16(v0); }
        if (c1 < nmax) { v1 = stg[row * 132 + c1]; op[c1] = __float2bfloat16(v1); }
        if (c2 < nmax) { v2 = stg[row * 132 + c2]; op[c2] = __float2bfloat16(v2); }
        if (c3 < nmax) { v3 = stg[row * 132 + c3]; op[c3] = __float2bfloat16(v3); }
        float mx = fmaxf(fmaxf(v0, v1), fmaxf(v2, v3));
#pragma unroll
        for (int o = 16; o > 0; o >>= 1)
            mx = fmaxf(mx, __shfl_xor_sync(0xffffffffu, mx, o));
        float s = 0.f;
        if (c0 < nmax) s += __expf(v0 - mx);
        if (c1 < nmax) s += __expf(v1 - mx);
        if (c2 < nmax) s += __expf(v2 - mx);
        if (c3 < nmax) s += __expf(v3 - mx);
#pragma unroll
        for (int o = 16; o > 0; o >>= 1)
            s += __shfl_xor_sync(0xffffffffu, s, o);
        if (lid == 0) {
            g_pmax[(size_t)r_out * NBLK_LG + blockIdx.x] = mx;
            g_psum[(size_t)r_out * NBLK_LG + blockIdx.x] = s;
        }
    }
}

// ================= lse reduce + final output (flat float4 stores) =================
__global__ void lse_reduce() {
    int row = blockIdx.x * 8 + (threadIdx.x >> 5);
    int lid = threadIdx.x & 31;
    float m = -INFINITY, s = 0.f;
    for (int i = lid; i < NBLK_LG; i += 32) {
        float m2 = g_pmax[(size_t)row * NBLK_LG + i];
        float s2 = g_psum[(size_t)row * NBLK_LG + i];
        if (m2 > m) { s = s * __expf(m - m2) + s2; m = m2; }
        else        { s += s2 * __expf(m2 - m); }
    }
#pragma unroll
    for (int o = 16; o > 0; o >>= 1) {
        float m2 = __shfl_xor_sync(0xffffffffu, m, o);
        float s2 = __shfl_xor_sync(0xffffffffu, s, o);
        if (m2 > m) { s = s * __expf(m - m2) + s2; m = m2; }
        else        { s += s2 * __expf(m2 - m); }
    }
    if (lid == 0) g_lse[row] = m + logf(s);
}

#define NOUT ((size_t)BB * TT * VOCAB1)   // 40961280
__global__ void final_out(float* __restrict__ out) {
    size_t g0 = ((size_t)blockIdx.x * blockDim.x + threadIdx.x) * 4;
    if (g0 >= NOUT) return;
    uint32_t row = (uint32_t)(g0 / VOCAB1);
    uint32_t col = (uint32_t)(g0 - (size_t)row * VOCAB1);
    if (col + 3 < VOCAB1 && g0 + 3 < NOUT) {
        const __nv_bfloat16* lp = g_lgb + (size_t)row * VP + col;
        float l = g_lse[row];
        float4 o;
        o.x = __bfloat162float(lp[0]) - l;
        o.y = __bfloat162float(lp[1]) - l;
        o.z = __bfloat162float(lp[2]) - l;
        o.w = __bfloat162float(lp[3]) - l;
        *reinterpret_cast<float4*>(out + g0) = o;   // 16B aligned (g0 % 4 == 0)
    } else {
        for (int j = 0; j < 4 && g0 + j < NOUT; j++) {
            size_t g = g0 + j;
            uint32_t r = (uint32_t)(g / VOCAB1);
            uint32_t c = (uint32_t)(g - (size_t)r * VOCAB1);
            out[g] = __bfloat162float(g_lgb[(size_t)r * VP + c]) - g_lse[r];
        }
    }
}

// ================= launch =================
extern "C" void kernel_launch(void* const* d_in, const int* in_sizes, int n_in,
                              void* d_out, int out_size) {
    const float* img_feat = (const float*)d_in[0];
    const int*   seq      = (const int*)d_in[1];
    const float* W_img    = (const float*)d_in[2];
    const float* b_img    = (const float*)d_in[3];
    const float* embed    = (const float*)d_in[4];
    const float* W_ih     = (const float*)d_in[5];
    const float* b_ih     = (const float*)d_in[6];
    const float* W_hh     = (const float*)d_in[7];
    const float* b_hh     = (const float*)d_in[8];
    const float* W_logit  = (const float*)d_in[9];
    const float* b_logit  = (const float*)d_in[10];
    float* out = (float*)d_out;

    float *gx, *bias2;
    __nv_bfloat16 *xsb, *lgb;
    unsigned char *hs8, *wl8;
    cudaGetSymbolAddress((void**)&gx,    g_gx);
    cudaGetSymbolAddress((void**)&bias2, g_bias2);
    cudaGetSymbolAddress((void**)&xsb,   g_xsb);
    cudaGetSymbolAddress((void**)&lgb,   g_lgb);
    cudaGetSymbolAddress((void**)&hs8,   g_hs8);
    cudaGetSymbolAddress((void**)&wl8,   g_wl8);
    __nv_bfloat16* wib;
    cudaGetSymbolAddress((void**)&wib,   g_wib);

    cudaFuncSetAttribute(bmma_gates,     cudaFuncAttributeMaxDynamicSharedMemorySize, LG_DSMEM);
    cudaFuncSetAttribute(bmma_logits8,   cudaFuncAttributeMaxDynamicSharedMemorySize, LG_DSMEM);
    cudaFuncSetAttribute(lstm_persist64, cudaFuncAttributeMaxDynamicSharedMemorySize, ST_SMEM);

    // launch order chosen so ncu (-s 5 -c 1) profiles lstm_persist64 (launch #6)
    init_gather<<<1216, 128>>>(seq, embed, b_ih, b_hh);                     // 1
    conv_all<<<CONV_BLOCKS, 256>>>(W_logit, W_ih, W_hh);                    // 2
    x0_ksplit<<<dim3(8, 8), 256>>>(img_feat, W_img);                        // 3
    x0_reduce<<<(BB * DIN) / 256, 256>>>(b_img);                            // 4
    bmma_gates<<<dim3(16, 10), 256, LG_DSMEM>>>(xsb, wib, bias2, gx);       // 5
    lstm_persist64<<<64, 256, ST_SMEM>>>();                                 // 6 <- profiled
    bmma_logits8<<<dim3(NBLK_LG, 10), 256, LG_DSMEM>>>(hs8, wl8, b_logit, lgb); // 7
    lse_reduce<<<BB * TT / 8, 256>>>();                                     // 8
    final_out<<<(int)((NOUT / 4 + 255) / 256), 256>>>(out);                 // 9
}